// round 14
// baseline (speedup 1.0000x reference)
#include <cuda_runtime.h>
#include <cuda_bf16.h>
#include <cstdint>

// Problem constants
#define BSZ 64
#define NN_ 256
#define TT_ 512
#define NT_ (NN_*TT_)          // 131072
#define BNT (BSZ*NN_*TT_)      // 8388608
#define BNN (BSZ*NN_*NN_)      // 4194304
#define NMAX 51                // 256/5
#define KCAT 1536              // 3*T concatenated Chebyshev inputs
#define CATN ((long)BSZ*NN_*KCAT)

// -------- scratch (device globals; no allocation allowed) --------
__device__ __align__(256) float g_sc [BNN];   // scores -> A (topk in place)
__device__ __align__(256) __nv_bfloat16 g_xlnh[BNT];
__device__ __align__(256) __nv_bfloat16 g_xlnl[BNT];
__device__ __align__(256) __nv_bfloat16 g_xph [BNT];
__device__ __align__(256) __nv_bfloat16 g_xpl [BNT];
__device__ __align__(256) __nv_bfloat16 g_sch [BNN];
__device__ __align__(256) __nv_bfloat16 g_scl [BNN];
__device__ __align__(256) __nv_bfloat16 g_cath[CATN];
__device__ __align__(256) __nv_bfloat16 g_catl[CATN];
__device__ __align__(256) __nv_bfloat16 g_liwh[TT_*TT_];
__device__ __align__(256) __nv_bfloat16 g_liwl[TT_*TT_];
__device__ __align__(256) __nv_bfloat16 g_chwh[KCAT*TT_];
__device__ __align__(256) __nv_bfloat16 g_chwl[KCAT*TT_];
__device__ float g_mu  [BSZ];
__device__ float g_rstd[BSZ];
__device__ float g_ps  [BSZ*8];
__device__ float g_pq  [BSZ*8];
__device__ float g_bps [NN_*4];
__device__ float g_bpq [NN_*4];
__device__ float g_bns [NN_];
__device__ float g_bnh [NN_];
__device__ __align__(256) float g_dinv[BSZ*NN_];

// ======================= helpers =======================
__device__ __forceinline__ uint32_t smem_u32(const void* p) {
    uint32_t a;
    asm("{ .reg .u64 t; cvta.to.shared.u64 t, %1; cvt.u32.u64 %0, t; }"
        : "=r"(a) : "l"(p));
    return a;
}
__device__ __forceinline__ void cpasync16(uint32_t dst, const void* src) {
    asm volatile("cp.async.cg.shared.global [%0], [%1], 16;"
                 :: "r"(dst), "l"(src) : "memory");
}
#define CP_COMMIT() asm volatile("cp.async.commit_group;" ::: "memory")
#define CP_WAIT0()  asm volatile("cp.async.wait_group 0;" ::: "memory")

__device__ __forceinline__ void ldsm_x4(uint32_t addr, uint32_t* r) {
    asm volatile("ldmatrix.sync.aligned.m8n8.x4.shared.b16 {%0,%1,%2,%3}, [%4];"
        : "=r"(r[0]), "=r"(r[1]), "=r"(r[2]), "=r"(r[3]) : "r"(addr));
}
__device__ __forceinline__ void ldsm_x4_t(uint32_t addr, uint32_t* r) {
    asm volatile("ldmatrix.sync.aligned.m8n8.x4.trans.shared.b16 {%0,%1,%2,%3}, [%4];"
        : "=r"(r[0]), "=r"(r[1]), "=r"(r[2]), "=r"(r[3]) : "r"(addr));
}
__device__ __forceinline__ void mma_bf16(float* c, const uint32_t* a,
                                         uint32_t b0, uint32_t b1) {
    asm volatile(
        "mma.sync.aligned.m16n8k16.row.col.f32.bf16.bf16.f32 "
        "{%0,%1,%2,%3}, {%4,%5,%6,%7}, {%8,%9}, {%0,%1,%2,%3};"
        : "+f"(c[0]), "+f"(c[1]), "+f"(c[2]), "+f"(c[3])
        : "r"(a[0]), "r"(a[1]), "r"(a[2]), "r"(a[3]), "r"(b0), "r"(b1));
}
__device__ __forceinline__ unsigned pack_bf2(float a, float b) {
    __nv_bfloat162 h = __floats2bfloat162_rn(a, b);
    return *reinterpret_cast<unsigned*>(&h);
}
__device__ __forceinline__ float2 bf2_to_f2(uint32_t u) {
    __nv_bfloat162 b = *reinterpret_cast<__nv_bfloat162*>(&u);
    return __bfloat1622float2(b);
}
__device__ __forceinline__ void split_bf(float v, float& hi, float& lo) {
    __nv_bfloat16 h = __float2bfloat16_rn(v);
    hi = __bfloat162float(h);
    lo = v - hi;
}
__device__ __forceinline__ void split4_store(float4 o, __nv_bfloat16* H,
                                             __nv_bfloat16* L, long idx) {
    float h0,h1,h2,h3,l0,l1,l2,l3;
    split_bf(o.x,h0,l0); split_bf(o.y,h1,l1);
    split_bf(o.z,h2,l2); split_bf(o.w,h3,l3);
    uint2 hh; hh.x = pack_bf2(h0,h1); hh.y = pack_bf2(h2,h3);
    uint2 ll; ll.x = pack_bf2(l0,l1); ll.y = pack_bf2(l2,l3);
    *(uint2*)(H + idx) = hh;
    *(uint2*)(L + idx) = ll;
}
// reconstruct 4 fp32 from h/l bf16 pair at idx (idx multiple of 4)
__device__ __forceinline__ float4 hl_load4(const __nv_bfloat16* H,
                                           const __nv_bfloat16* L, long idx) {
    uint2 hh = *(const uint2*)(H + idx);
    uint2 ll = *(const uint2*)(L + idx);
    float2 h01 = bf2_to_f2(hh.x), h23 = bf2_to_f2(hh.y);
    float2 l01 = bf2_to_f2(ll.x), l23 = bf2_to_f2(ll.y);
    return make_float4(h01.x + l01.x, h01.y + l01.y, h23.x + l23.x, h23.y + l23.y);
}

// ======================= GEMM (bf16 3-product, cp.async + ldmatrix) ==========
// C = alpha*A@op(B) + beta*(Dh+Dl) (+bias) (+relu); optional split outputs Ch/Cl.
// A (hi/lo bf16): MxK row-major. B: TRANSB ? NxK row-major : KxN row-major.
// CTA tile 128x128, K-chunk 16, 2-stage cp.async pipeline, ONE sync per chunk.
#define ATILE 10240
#define BUFSZ 20480
#define SMEM_GEMM (2*BUFSZ)    // 40960 < 48KB default limit

template<bool TRANSB>
__global__ __launch_bounds__(256, 2)
void gemm_tc_kernel(const __nv_bfloat16* __restrict__ Ahg, const __nv_bfloat16* __restrict__ Alg,
                    const __nv_bfloat16* __restrict__ Bhg, const __nv_bfloat16* __restrict__ Blg,
                    const __nv_bfloat16* __restrict__ Dh, const __nv_bfloat16* __restrict__ Dl,
                    const float* __restrict__ bias,
                    float* __restrict__ C,
                    __nv_bfloat16* __restrict__ Ch, __nv_bfloat16* __restrict__ Cl,
                    int Kd, int ldA, int ldB, int ldC, int ldD,
                    long sA, long sB, long sC, long sD,
                    float alpha, float beta, int relu) {
    extern __shared__ __align__(128) char smem[];
    uint32_t sb = smem_u32(smem);

    int tid = threadIdx.x, lane = tid & 31, warp = tid >> 5;
    int z = blockIdx.z;
    Ahg += (long)z * sA; Alg += (long)z * sA;
    Bhg += (long)z * sB; Blg += (long)z * sB;
    if (C)  C  += (long)z * sC;
    if (Ch) { Ch += (long)z * sC; Cl += (long)z * sC; }
    if (Dh) { Dh += (long)z * sD; Dl += (long)z * sD; }
    int rowBase = blockIdx.y * 128;
    int colBase = blockIdx.x * 128;

    int g = lane >> 2, t4 = lane & 3;
    int mW = (warp >> 1) * 32, nW = (warp & 1) * 64;

    // per-lane ldmatrix byte offsets
    uint32_t aoff = (uint32_t)((mW + (lane & 15)) * 80 + ((lane >> 4) << 4));
    uint32_t boff;
    if (TRANSB)
        boff = (uint32_t)((nW + (lane & 7) + ((lane >> 4) << 3)) * 80
                          + (((lane >> 3) & 1) << 4));
    else
        boff = (uint32_t)(((lane & 7) + (((lane >> 3) & 1) << 3)) * 528
                          + (nW + ((lane >> 4) << 3)) * 2);

    float acc[2][8][4];
#pragma unroll
    for (int t = 0; t < 2; t++)
#pragma unroll
        for (int j = 0; j < 8; j++)
#pragma unroll
            for (int c = 0; c < 4; c++) acc[t][j][c] = 0.f;

    int nCh = Kd >> 4;

    auto FILL = [&](int ch, int buf) {
        uint32_t ab = sb + buf * BUFSZ;
        uint32_t bb = ab + ATILE;
        int kt = ch << 4;
#pragma unroll
        for (int i = 0; i < 2; i++) {
            int idx = tid + (i << 8);
            int r = idx >> 2, c = idx & 3;                   // c: 0,1 hi; 2,3 lo
            const __nv_bfloat16* src = (c < 2 ? Ahg : Alg)
                + (long)(rowBase + r) * ldA + kt + (c & 1) * 8;
            cpasync16(ab + r * 80 + c * 16, src);
        }
        if (TRANSB) {
#pragma unroll
            for (int i = 0; i < 2; i++) {
                int idx = tid + (i << 8);
                int r = idx >> 2, c = idx & 3;
                const __nv_bfloat16* src = (c < 2 ? Bhg : Blg)
                    + (long)(colBase + r) * ldB + kt + (c & 1) * 8;
                cpasync16(bb + r * 80 + c * 16, src);
            }
        } else {
#pragma unroll
            for (int i = 0; i < 2; i++) {
                int idx = tid + (i << 8);
                int k = idx >> 5, c = idx & 31;              // c<16 hi, else lo
                const __nv_bfloat16* src = (c < 16 ? Bhg : Blg)
                    + (long)(kt + k) * ldB + colBase + (c & 15) * 8;
                cpasync16(bb + k * 528 + c * 16, src);
            }
        }
    };

    auto MMASTEP = [&](int buf) {
        uint32_t ab = sb + buf * BUFSZ, bb = ab + ATILE;
        uint32_t ahf[2][4], alf[2][4];
        ldsm_x4(ab + aoff,        ahf[0]);
        ldsm_x4(ab + aoff + 1280, ahf[1]);
        ldsm_x4(ab + aoff + 32,        alf[0]);
        ldsm_x4(ab + aoff + 32 + 1280, alf[1]);
#pragma unroll
        for (int jt = 0; jt < 4; jt++) {
            uint32_t bh[4], bl[4];
            if (TRANSB) {
                ldsm_x4(bb + boff + jt * 1280,      bh);
                ldsm_x4(bb + boff + jt * 1280 + 32, bl);
            } else {
                ldsm_x4_t(bb + boff + jt * 32,       bh);
                ldsm_x4_t(bb + boff + jt * 32 + 256, bl);
            }
#pragma unroll
            for (int j2 = 0; j2 < 2; j2++) {
                int j = jt * 2 + j2;
#pragma unroll
                for (int mt = 0; mt < 2; mt++) {
                    mma_bf16(acc[mt][j], ahf[mt], bh[j2*2], bh[j2*2+1]);
                    mma_bf16(acc[mt][j], alf[mt], bh[j2*2], bh[j2*2+1]);
                    mma_bf16(acc[mt][j], ahf[mt], bl[j2*2], bl[j2*2+1]);
                }
            }
        }
    };

    // Single-sync pipeline (R12 proven).
    FILL(0, 0); CP_COMMIT();
    for (int c = 0; c < nCh; c++) {
        CP_WAIT0();
        __syncthreads();
        if (c + 1 < nCh) { FILL(c + 1, (c + 1) & 1); CP_COMMIT(); }
        MMASTEP(c & 1);
    }

    // ---- epilogue ----
#pragma unroll
    for (int mt = 0; mt < 2; mt++) {
#pragma unroll
        for (int j = 0; j < 8; j++) {
            int c0 = colBase + nW + j * 8 + t4 * 2;
            float bs0 = 0.f, bs1 = 0.f;
            if (bias) { bs0 = bias[c0]; bs1 = bias[c0 + 1]; }
#pragma unroll
            for (int rr = 0; rr < 2; rr++) {
                int r = rowBase + mW + mt * 16 + g + rr * 8;
                float v0 = alpha * acc[mt][j][rr * 2 + 0];
                float v1 = alpha * acc[mt][j][rr * 2 + 1];
                if (Dh) {
                    long db = (long)r * ldD + c0;
                    float2 dh = bf2_to_f2(*(const uint32_t*)(Dh + db));
                    float2 dl = bf2_to_f2(*(const uint32_t*)(Dl + db));
                    v0 += beta * (dh.x + dl.x);
                    v1 += beta * (dh.y + dl.y);
                }
                v0 += bs0; v1 += bs1;
                if (relu) { v0 = fmaxf(v0, 0.f); v1 = fmaxf(v1, 0.f); }
                long cb = (long)r * ldC + c0;
                if (C) { *(float2*)(C + cb) = make_float2(v0, v1); }
                if (Ch) {
                    float h0,l0,h1,l1;
                    split_bf(v0, h0, l0); split_bf(v1, h1, l1);
                    *(uint32_t*)(Ch + cb) = pack_bf2(h0, h1);
                    *(uint32_t*)(Cl + cb) = pack_bf2(l0, l1);
                }
            }
        }
    }
}

// ======================= elementwise kernels =======================
// LayerNorm stats, stage 1: grid (BSZ, 8), each block reduces NT_/8 elements.
__global__ void ln_stats1_kernel(const float* __restrict__ x) {
    int b = blockIdx.x, part = blockIdx.y;
    const float4* xb = (const float4*)(x + (long)b * NT_ + part * (NT_/8));
    float s = 0.f, q = 0.f;
    for (int i = threadIdx.x; i < NT_/8/4; i += 256) {
        float4 v = xb[i];
        s += v.x + v.y + v.z + v.w;
        q += v.x*v.x + v.y*v.y + v.z*v.z + v.w*v.w;
    }
    __shared__ float ss[256], sq[256];
    ss[threadIdx.x] = s; sq[threadIdx.x] = q;
    __syncthreads();
    for (int o = 128; o > 0; o >>= 1) {
        if (threadIdx.x < o) { ss[threadIdx.x] += ss[threadIdx.x+o]; sq[threadIdx.x] += sq[threadIdx.x+o]; }
        __syncthreads();
    }
    if (threadIdx.x == 0) {
        g_ps[b * 8 + part] = ss[0];
        g_pq[b * 8 + part] = sq[0];
    }
}

// stage 2: one block, 64 threads, fixed summation order (deterministic)
__global__ void ln_stats2_kernel() {
    int b = threadIdx.x;
    if (b < BSZ) {
        float s = 0.f, q = 0.f;
        for (int i = 0; i < 8; i++) { s += g_ps[b*8+i]; q += g_pq[b*8+i]; }
        float mu  = s / (float)NT_;
        float var = q / (float)NT_ - mu * mu;
        g_mu[b] = mu;
        g_rstd[b] = rsqrtf(var + 1e-5f);
    }
}

// x_ln -> h/l bf16 only (no fp32 mirror)
__global__ void ln_apply_kernel(const float* __restrict__ x,
                                const float* __restrict__ lw,
                                const float* __restrict__ lb) {
    int i4 = blockIdx.x * 256 + threadIdx.x;
    int base = i4 * 4;
    int b  = base / NT_;
    int nt4 = (base % NT_) / 4;
    float mu = g_mu[b], rs = g_rstd[b];
    float4 v = ((const float4*)x)[i4];
    float4 w = ((const float4*)lw)[nt4];
    float4 bb = ((const float4*)lb)[nt4];
    float4 o;
    o.x = (v.x - mu) * rs * w.x + bb.x;
    o.y = (v.y - mu) * rs * w.y + bb.y;
    o.z = (v.z - mu) * rs * w.z + bb.z;
    o.w = (v.w - mu) * rs * w.w + bb.w;
    split4_store(o, g_xlnh, g_xlnl, (long)base);
}

// BatchNorm stats stage 1: grid (NN_, 4); block (n, p) reduces batches
// [p*16, p*16+16) for node n. Fixed per-part order -> deterministic combine.
__global__ void bn_stats1_kernel() {
    int n = blockIdx.x, part = blockIdx.y;
    float s = 0.f, q = 0.f;
    for (int i = threadIdx.x; i < (16*TT_)/4; i += 256) {
        int base = i * 4;
        int b = part * 16 + base / TT_;
        int t = base % TT_;
        float4 v = hl_load4(g_xlnh, g_xlnl, ((long)b * NN_ + n) * TT_ + t);
        s += v.x + v.y + v.z + v.w;
        q += v.x*v.x + v.y*v.y + v.z*v.z + v.w*v.w;
    }
    __shared__ float ss[256], sq[256];
    ss[threadIdx.x] = s; sq[threadIdx.x] = q;
    __syncthreads();
    for (int o = 128; o > 0; o >>= 1) {
        if (threadIdx.x < o) { ss[threadIdx.x] += ss[threadIdx.x+o]; sq[threadIdx.x] += sq[threadIdx.x+o]; }
        __syncthreads();
    }
    if (threadIdx.x == 0) {
        g_bps[n * 4 + part] = ss[0];
        g_bpq[n * 4 + part] = sq[0];
    }
}

// BatchNorm stats stage 2: one block, 256 threads, fixed summation order
__global__ void bn_stats2_kernel(const float* __restrict__ bg,
                                 const float* __restrict__ bb) {
    int n = threadIdx.x;
    float s = 0.f, q = 0.f;
    for (int i = 0; i < 4; i++) { s += g_bps[n*4+i]; q += g_bpq[n*4+i]; }
    float cnt  = (float)(BSZ * TT_);
    float mean = s / cnt;
    float var  = q / cnt - mean * mean;
    float sc   = bg[n] * rsqrtf(var + 1e-5f);
    g_bns[n] = sc;
    g_bnh[n] = bb[n] - mean * sc;
}

// x_bn -> cat slot 0 (bf16 h/l, ld KCAT) only (no fp32 mirror)
__global__ void bn_apply_kernel() {
    int i4 = blockIdx.x * 256 + threadIdx.x;
    int base = i4 * 4;
    int row = base / TT_;
    int col = base % TT_;
    int n = row & (NN_ - 1);
    float sc = g_bns[n], sh = g_bnh[n];
    float4 v = hl_load4(g_xlnh, g_xlnl, (long)base);
    float4 o;
    o.x = v.x * sc + sh; o.y = v.y * sc + sh;
    o.z = v.z * sc + sh; o.w = v.w * sc + sh;
    split4_store(o, g_cath, g_catl, (long)row * KCAT + col);
}

__global__ void convert_kernel(const float* __restrict__ src,
                               __nv_bfloat16* __restrict__ h,
                               __nv_bfloat16* __restrict__ l) {
    int i4 = blockIdx.x * 256 + threadIdx.x;
    float4 v = ((const float4*)src)[i4];
    split4_store(v, h, l, (long)i4 * 4);
}

// bitonic-sort top-k (R8/R12 proven)
__global__ void topk_kernel(const float* __restrict__ dis) {
    int row = blockIdx.x;
    int n = row & (NN_ - 1);
    int tid = threadIdx.x;
    __shared__ float raw[256], srt[256];
    float v = g_sc[(long)row * NN_ + tid];
    raw[tid] = v; srt[tid] = v;
    __syncthreads();
    for (unsigned k = 2; k <= 256; k <<= 1) {
        for (unsigned j = k >> 1; j > 0; j >>= 1) {
            unsigned ixj = tid ^ j;
            if (ixj > (unsigned)tid) {
                float a = srt[tid], b2 = srt[ixj];
                bool asc = ((tid & k) == 0);
                if ((a > b2) == asc) { srt[tid] = b2; srt[ixj] = a; }
            }
            __syncthreads();
        }
    }
    float kth = srt[256 - NMAX];
    __syncthreads();
    float a = (raw[tid] >= kth) ? raw[tid] : 0.f;
    a += dis[n * NN_ + tid];
    a = fmaxf(a, 0.f);
    srt[tid] = a;
    __syncthreads();
    for (int o = 128; o > 0; o >>= 1) {
        if (tid < o) srt[tid] += srt[tid + o];
        __syncthreads();
    }
    g_sc[(long)row * NN_ + tid] = a;
    if (tid == 0) g_dinv[row] = rsqrtf(srt[0] + 1e-10f);
}

// L = D^-1/2 A D^-1/2 -> bf16 h/l
__global__ void lscale_kernel() {
    int i4 = blockIdx.x * 256 + threadIdx.x;
    int base = i4 * 4;
    int b   = base / (NN_ * NN_);
    int rem = base % (NN_ * NN_);
    int n   = rem / NN_;
    int m   = rem % NN_;
    float dn = g_dinv[b * NN_ + n];
    const float* dm = &g_dinv[b * NN_ + m];
    float4 a = ((const float4*)g_sc)[i4];
    a.x *= dn * dm[0];
    a.y *= dn * dm[1];
    a.z *= dn * dm[2];
    a.w *= dn * dm[3];
    split4_store(a, g_sch, g_scl, (long)base);
}

// ======================= launch =======================
extern "C" void kernel_launch(void* const* d_in, const int* in_sizes, int n_in,
                              void* d_out, int out_size) {
    const float* x      = (const float*)d_in[0];
    const float* dis    = (const float*)d_in[1];
    const float* ln_w   = (const float*)d_in[2];
    const float* ln_b   = (const float*)d_in[3];
    const float* bn_g   = (const float*)d_in[4];
    const float* bn_b   = (const float*)d_in[5];
    const float* li_w   = (const float*)d_in[6];
    const float* li_b   = (const float*)d_in[7];
    const float* cheb_w = (const float*)d_in[8];
    const float* cheb_b = (const float*)d_in[9];
    float* out = (float*)d_out;

    __nv_bfloat16 *xlnh, *xlnl, *xph, *xpl, *sch, *scl, *cath, *catl;
    __nv_bfloat16 *liwh, *liwl, *chwh, *chwl;
    float *sc;
    cudaGetSymbolAddress((void**)&xlnh, g_xlnh);
    cudaGetSymbolAddress((void**)&xlnl, g_xlnl);
    cudaGetSymbolAddress((void**)&xph,  g_xph);
    cudaGetSymbolAddress((void**)&xpl,  g_xpl);
    cudaGetSymbolAddress((void**)&sch,  g_sch);
    cudaGetSymbolAddress((void**)&scl,  g_scl);
    cudaGetSymbolAddress((void**)&cath, g_cath);
    cudaGetSymbolAddress((void**)&catl, g_catl);
    cudaGetSymbolAddress((void**)&liwh, g_liwh);
    cudaGetSymbolAddress((void**)&liwl, g_liwl);
    cudaGetSymbolAddress((void**)&chwh, g_chwh);
    cudaGetSymbolAddress((void**)&chwl, g_chwl);
    cudaGetSymbolAddress((void**)&sc,   g_sc);

    // 1. LayerNorm (2-stage stats) -> xln h/l
    {
        dim3 g1(BSZ, 8, 1);
        ln_stats1_kernel<<<g1, 256>>>(x);
        ln_stats2_kernel<<<1, 64>>>();
    }
    ln_apply_kernel<<<BNT/4/256, 256>>>(x, ln_w, ln_b);

    // 2. BatchNorm (2-stage stats) -> cat slot0 h/l
    {
        dim3 g1(NN_, 4, 1);
        bn_stats1_kernel<<<g1, 256>>>();
        bn_stats2_kernel<<<1, NN_>>>(bn_g, bn_b);
    }
    bn_apply_kernel<<<BNT/4/256, 256>>>();

    // 3. weight conversion
    convert_kernel<<<(TT_*TT_)/4/256, 256>>>(li_w, liwh, liwl);
    convert_kernel<<<(KCAT*TT_)/4/256, 256>>>(cheb_w, chwh, chwl);

    // 4. xp = x_ln @ li_w^T + li_b  -> xp h/l
    {
        dim3 g(TT_/128, (BSZ*NN_)/128, 1);
        gemm_tc_kernel<true><<<g, 256, SMEM_GEMM>>>(
            xlnh, xlnl, liwh, liwl, 0, 0, li_b, 0, xph, xpl,
            TT_, TT_, TT_, TT_, 0, 0, 0, 0, 0, 1.f, 0.f, 0);
    }
    // 5. scores = xp @ xp^T  -> sc fp32
    {
        dim3 g(NN_/128, NN_/128, BSZ);
        gemm_tc_kernel<true><<<g, 256, SMEM_GEMM>>>(
            xph, xpl, xph, xpl, 0, 0, 0, sc, 0, 0,
            TT_, TT_, TT_, NN_, 0,
            (long)NT_, (long)NT_, (long)NN_*NN_, 0, 1.f, 0.f, 0);
    }
    // 6. top-k + dis prior + relu + degree
    topk_kernel<<<BSZ*NN_, 256>>>(dis);
    // 7. L -> sc h/l
    lscale_kernel<<<BNN/4/256, 256>>>();

    // 8. Tx1 = L @ Tx0 -> cat slot1 h/l
    {
        dim3 g(TT_/128, NN_/128, BSZ);
        gemm_tc_kernel<false><<<g, 256, SMEM_GEMM>>>(
            sch, scl, cath, catl, 0, 0, 0, 0, cath + TT_, catl + TT_,
            NN_, NN_, KCAT, KCAT, 0,
            (long)NN_*NN_, (long)NN_*KCAT, (long)NN_*KCAT, 0, 1.f, 0.f, 0);
    }
    // 9. Tx2 = 2*L @ Tx1 - Tx0 -> cat slot2 h/l  (D = cat slot0 h/l)
    {
        dim3 g(TT_/128, NN_/128, BSZ);
        gemm_tc_kernel<false><<<g, 256, SMEM_GEMM>>>(
            sch, scl, cath + TT_, catl + TT_, cath, catl, 0, 0,
            cath + 2*TT_, catl + 2*TT_,
            NN_, NN_, KCAT, KCAT, KCAT,
            (long)NN_*NN_, (long)NN_*KCAT, (long)NN_*KCAT, (long)NN_*KCAT,
            2.f, -1.f, 0);
    }
    // 10. out = relu(cat @ cheb_flat + cheb_b)
    {
        dim3 g(TT_/128, (BSZ*NN_)/128, 1);
        gemm_tc_kernel<false><<<g, 256, SMEM_GEMM>>>(
            cath, catl, chwh, chwl, 0, 0, cheb_b, out, 0, 0,
            KCAT, KCAT, TT_, TT_, 0, 0, 0, 0, 0, 1.f, 0.f, 1);
    }
}

// round 15
// speedup vs baseline: 1.0106x; 1.0106x over previous
#include <cuda_runtime.h>
#include <cuda_bf16.h>
#include <cstdint>

// Problem constants
#define BSZ 64
#define NN_ 256
#define TT_ 512
#define NT_ (NN_*TT_)          // 131072
#define BNT (BSZ*NN_*TT_)      // 8388608
#define BNN (BSZ*NN_*NN_)      // 4194304
#define NMAX 51                // 256/5
#define KCAT 1536              // 3*T concatenated Chebyshev inputs
#define CATN ((long)BSZ*NN_*KCAT)

// -------- scratch (device globals; no allocation allowed) --------
__device__ __align__(256) float g_sc [BNN];   // scores -> A (topk in place)
__device__ __align__(256) __nv_bfloat16 g_xlnh[BNT];
__device__ __align__(256) __nv_bfloat16 g_xlnl[BNT];
__device__ __align__(256) __nv_bfloat16 g_xph [BNT];
__device__ __align__(256) __nv_bfloat16 g_xpl [BNT];
__device__ __align__(256) __nv_bfloat16 g_sch [BNN];
__device__ __align__(256) __nv_bfloat16 g_scl [BNN];
__device__ __align__(256) __nv_bfloat16 g_cath[CATN];
__device__ __align__(256) __nv_bfloat16 g_catl[CATN];
__device__ __align__(256) __nv_bfloat16 g_liwh[TT_*TT_];
__device__ __align__(256) __nv_bfloat16 g_liwl[TT_*TT_];
__device__ __align__(256) __nv_bfloat16 g_chwh[KCAT*TT_];
__device__ __align__(256) __nv_bfloat16 g_chwl[KCAT*TT_];
__device__ float g_mu  [BSZ];
__device__ float g_rstd[BSZ];
__device__ float g_ps  [BSZ*8];
__device__ float g_pq  [BSZ*8];
__device__ float g_bps [NN_*4];
__device__ float g_bpq [NN_*4];
__device__ float g_bns [NN_];
__device__ float g_bnh [NN_];
__device__ __align__(256) float g_dinv[BSZ*NN_];

// ======================= helpers =======================
__device__ __forceinline__ uint32_t smem_u32(const void* p) {
    uint32_t a;
    asm("{ .reg .u64 t; cvta.to.shared.u64 t, %1; cvt.u32.u64 %0, t; }"
        : "=r"(a) : "l"(p));
    return a;
}
__device__ __forceinline__ void cpasync16(uint32_t dst, const void* src) {
    asm volatile("cp.async.cg.shared.global [%0], [%1], 16;"
                 :: "r"(dst), "l"(src) : "memory");
}
#define CP_COMMIT() asm volatile("cp.async.commit_group;" ::: "memory")
#define CP_WAIT0()  asm volatile("cp.async.wait_group 0;" ::: "memory")
#define CP_WAIT1()  asm volatile("cp.async.wait_group 1;" ::: "memory")

__device__ __forceinline__ void ldsm_x4(uint32_t addr, uint32_t* r) {
    asm volatile("ldmatrix.sync.aligned.m8n8.x4.shared.b16 {%0,%1,%2,%3}, [%4];"
        : "=r"(r[0]), "=r"(r[1]), "=r"(r[2]), "=r"(r[3]) : "r"(addr));
}
__device__ __forceinline__ void ldsm_x4_t(uint32_t addr, uint32_t* r) {
    asm volatile("ldmatrix.sync.aligned.m8n8.x4.trans.shared.b16 {%0,%1,%2,%3}, [%4];"
        : "=r"(r[0]), "=r"(r[1]), "=r"(r[2]), "=r"(r[3]) : "r"(addr));
}
__device__ __forceinline__ void mma_bf16(float* c, const uint32_t* a,
                                         uint32_t b0, uint32_t b1) {
    asm volatile(
        "mma.sync.aligned.m16n8k16.row.col.f32.bf16.bf16.f32 "
        "{%0,%1,%2,%3}, {%4,%5,%6,%7}, {%8,%9}, {%0,%1,%2,%3};"
        : "+f"(c[0]), "+f"(c[1]), "+f"(c[2]), "+f"(c[3])
        : "r"(a[0]), "r"(a[1]), "r"(a[2]), "r"(a[3]), "r"(b0), "r"(b1));
}
__device__ __forceinline__ unsigned pack_bf2(float a, float b) {
    __nv_bfloat162 h = __floats2bfloat162_rn(a, b);
    return *reinterpret_cast<unsigned*>(&h);
}
__device__ __forceinline__ float2 bf2_to_f2(uint32_t u) {
    __nv_bfloat162 b = *reinterpret_cast<__nv_bfloat162*>(&u);
    return __bfloat1622float2(b);
}
__device__ __forceinline__ void split_bf(float v, float& hi, float& lo) {
    __nv_bfloat16 h = __float2bfloat16_rn(v);
    hi = __bfloat162float(h);
    lo = v - hi;
}
__device__ __forceinline__ void split4_store(float4 o, __nv_bfloat16* H,
                                             __nv_bfloat16* L, long idx) {
    float h0,h1,h2,h3,l0,l1,l2,l3;
    split_bf(o.x,h0,l0); split_bf(o.y,h1,l1);
    split_bf(o.z,h2,l2); split_bf(o.w,h3,l3);
    uint2 hh; hh.x = pack_bf2(h0,h1); hh.y = pack_bf2(h2,h3);
    uint2 ll; ll.x = pack_bf2(l0,l1); ll.y = pack_bf2(l2,l3);
    *(uint2*)(H + idx) = hh;
    *(uint2*)(L + idx) = ll;
}
// reconstruct 4 fp32 from h/l bf16 pair at idx (idx multiple of 4)
__device__ __forceinline__ float4 hl_load4(const __nv_bfloat16* H,
                                           const __nv_bfloat16* L, long idx) {
    uint2 hh = *(const uint2*)(H + idx);
    uint2 ll = *(const uint2*)(L + idx);
    float2 h01 = bf2_to_f2(hh.x), h23 = bf2_to_f2(hh.y);
    float2 l01 = bf2_to_f2(ll.x), l23 = bf2_to_f2(ll.y);
    return make_float4(h01.x + l01.x, h01.y + l01.y, h23.x + l23.x, h23.y + l23.y);
}

// ======================= GEMM (bf16 3-product, cp.async + ldmatrix) ==========
// C = alpha*A@op(B) + beta*(Dh+Dl) (+bias) (+relu); optional split outputs Ch/Cl.
// A (hi/lo bf16): MxK row-major. B: TRANSB ? NxK row-major : KxN row-major.
// CTA tile 128x128, K-chunk 16, 3-stage cp.async ring (fill depth 2),
// ONE sync per chunk. 60KB dynamic smem (opt-in).
#define ATILE 10240
#define BUFSZ 20480
#define SMEM_GEMM (3*BUFSZ)    // 61440, opt-in via cudaFuncSetAttribute

template<bool TRANSB>
__global__ __launch_bounds__(256, 2)
void gemm_tc_kernel(const __nv_bfloat16* __restrict__ Ahg, const __nv_bfloat16* __restrict__ Alg,
                    const __nv_bfloat16* __restrict__ Bhg, const __nv_bfloat16* __restrict__ Blg,
                    const __nv_bfloat16* __restrict__ Dh, const __nv_bfloat16* __restrict__ Dl,
                    const float* __restrict__ bias,
                    float* __restrict__ C,
                    __nv_bfloat16* __restrict__ Ch, __nv_bfloat16* __restrict__ Cl,
                    int Kd, int ldA, int ldB, int ldC, int ldD,
                    long sA, long sB, long sC, long sD,
                    float alpha, float beta, int relu) {
    extern __shared__ __align__(128) char smem[];
    uint32_t sb = smem_u32(smem);

    int tid = threadIdx.x, lane = tid & 31, warp = tid >> 5;
    int z = blockIdx.z;
    Ahg += (long)z * sA; Alg += (long)z * sA;
    Bhg += (long)z * sB; Blg += (long)z * sB;
    if (C)  C  += (long)z * sC;
    if (Ch) { Ch += (long)z * sC; Cl += (long)z * sC; }
    if (Dh) { Dh += (long)z * sD; Dl += (long)z * sD; }
    int rowBase = blockIdx.y * 128;
    int colBase = blockIdx.x * 128;

    int g = lane >> 2, t4 = lane & 3;
    int mW = (warp >> 1) * 32, nW = (warp & 1) * 64;

    // per-lane ldmatrix byte offsets
    uint32_t aoff = (uint32_t)((mW + (lane & 15)) * 80 + ((lane >> 4) << 4));
    uint32_t boff;
    if (TRANSB)
        boff = (uint32_t)((nW + (lane & 7) + ((lane >> 4) << 3)) * 80
                          + (((lane >> 3) & 1) << 4));
    else
        boff = (uint32_t)(((lane & 7) + (((lane >> 3) & 1) << 3)) * 528
                          + (nW + ((lane >> 4) << 3)) * 2);

    float acc[2][8][4];
#pragma unroll
    for (int t = 0; t < 2; t++)
#pragma unroll
        for (int j = 0; j < 8; j++)
#pragma unroll
            for (int c = 0; c < 4; c++) acc[t][j][c] = 0.f;

    int nCh = Kd >> 4;

    auto FILL = [&](int ch, int buf) {
        uint32_t ab = sb + buf * BUFSZ;
        uint32_t bb = ab + ATILE;
        int kt = ch << 4;
#pragma unroll
        for (int i = 0; i < 2; i++) {
            int idx = tid + (i << 8);
            int r = idx >> 2, c = idx & 3;                   // c: 0,1 hi; 2,3 lo
            const __nv_bfloat16* src = (c < 2 ? Ahg : Alg)
                + (long)(rowBase + r) * ldA + kt + (c & 1) * 8;
            cpasync16(ab + r * 80 + c * 16, src);
        }
        if (TRANSB) {
#pragma unroll
            for (int i = 0; i < 2; i++) {
                int idx = tid + (i << 8);
                int r = idx >> 2, c = idx & 3;
                const __nv_bfloat16* src = (c < 2 ? Bhg : Blg)
                    + (long)(colBase + r) * ldB + kt + (c & 1) * 8;
                cpasync16(bb + r * 80 + c * 16, src);
            }
        } else {
#pragma unroll
            for (int i = 0; i < 2; i++) {
                int idx = tid + (i << 8);
                int k = idx >> 5, c = idx & 31;              // c<16 hi, else lo
                const __nv_bfloat16* src = (c < 16 ? Bhg : Blg)
                    + (long)(kt + k) * ldB + colBase + (c & 15) * 8;
                cpasync16(bb + k * 528 + c * 16, src);
            }
        }
    };

    auto MMASTEP = [&](int buf) {
        uint32_t ab = sb + buf * BUFSZ, bb = ab + ATILE;
        uint32_t ahf[2][4], alf[2][4];
        ldsm_x4(ab + aoff,        ahf[0]);
        ldsm_x4(ab + aoff + 1280, ahf[1]);
        ldsm_x4(ab + aoff + 32,        alf[0]);
        ldsm_x4(ab + aoff + 32 + 1280, alf[1]);
#pragma unroll
        for (int jt = 0; jt < 4; jt++) {
            uint32_t bh[4], bl[4];
            if (TRANSB) {
                ldsm_x4(bb + boff + jt * 1280,      bh);
                ldsm_x4(bb + boff + jt * 1280 + 32, bl);
            } else {
                ldsm_x4_t(bb + boff + jt * 32,       bh);
                ldsm_x4_t(bb + boff + jt * 32 + 256, bl);
            }
#pragma unroll
            for (int j2 = 0; j2 < 2; j2++) {
                int j = jt * 2 + j2;
#pragma unroll
                for (int mt = 0; mt < 2; mt++) {
                    mma_bf16(acc[mt][j], ahf[mt], bh[j2*2], bh[j2*2+1]);
                    mma_bf16(acc[mt][j], alf[mt], bh[j2*2], bh[j2*2+1]);
                    mma_bf16(acc[mt][j], ahf[mt], bl[j2*2], bl[j2*2+1]);
                }
            }
        }
    };

    // 3-stage ring, fill depth 2, one sync per chunk:
    //   iter c: wait fill(c) (allow fill(c+1) in flight) -> sync
    //   -> FILL(c+2) into buf (c+2)%3 (last read by MMASTEP(c-1): ordered by sync)
    //   -> MMASTEP(c)
    int mod3[3] = {0, 1, 2};
    FILL(0, 0); CP_COMMIT();
    if (nCh > 1) { FILL(1, 1); CP_COMMIT(); }
    int bcur = 0, bnext2 = 2;
    for (int c = 0; c < nCh; c++) {
        if (c + 1 < nCh) CP_WAIT1();
        else             CP_WAIT0();
        __syncthreads();
        if (c + 2 < nCh) { FILL(c + 2, bnext2); CP_COMMIT(); }
        MMASTEP(bcur);
        bcur = (bcur == 2) ? 0 : bcur + 1;
        bnext2 = (bnext2 == 2) ? 0 : bnext2 + 1;
    }
    (void)mod3;

    // ---- epilogue ----
#pragma unroll
    for (int mt = 0; mt < 2; mt++) {
#pragma unroll
        for (int j = 0; j < 8; j++) {
            int c0 = colBase + nW + j * 8 + t4 * 2;
            float bs0 = 0.f, bs1 = 0.f;
            if (bias) { bs0 = bias[c0]; bs1 = bias[c0 + 1]; }
#pragma unroll
            for (int rr = 0; rr < 2; rr++) {
                int r = rowBase + mW + mt * 16 + g + rr * 8;
                float v0 = alpha * acc[mt][j][rr * 2 + 0];
                float v1 = alpha * acc[mt][j][rr * 2 + 1];
                if (Dh) {
                    long db = (long)r * ldD + c0;
                    float2 dh = bf2_to_f2(*(const uint32_t*)(Dh + db));
                    float2 dl = bf2_to_f2(*(const uint32_t*)(Dl + db));
                    v0 += beta * (dh.x + dl.x);
                    v1 += beta * (dh.y + dl.y);
                }
                v0 += bs0; v1 += bs1;
                if (relu) { v0 = fmaxf(v0, 0.f); v1 = fmaxf(v1, 0.f); }
                long cb = (long)r * ldC + c0;
                if (C) { *(float2*)(C + cb) = make_float2(v0, v1); }
                if (Ch) {
                    float h0,l0,h1,l1;
                    split_bf(v0, h0, l0); split_bf(v1, h1, l1);
                    *(uint32_t*)(Ch + cb) = pack_bf2(h0, h1);
                    *(uint32_t*)(Cl + cb) = pack_bf2(l0, l1);
                }
            }
        }
    }
}

// ======================= elementwise kernels =======================
// LayerNorm stats, stage 1: grid (BSZ, 8), each block reduces NT_/8 elements.
__global__ void ln_stats1_kernel(const float* __restrict__ x) {
    int b = blockIdx.x, part = blockIdx.y;
    const float4* xb = (const float4*)(x + (long)b * NT_ + part * (NT_/8));
    float s = 0.f, q = 0.f;
    for (int i = threadIdx.x; i < NT_/8/4; i += 256) {
        float4 v = xb[i];
        s += v.x + v.y + v.z + v.w;
        q += v.x*v.x + v.y*v.y + v.z*v.z + v.w*v.w;
    }
    __shared__ float ss[256], sq[256];
    ss[threadIdx.x] = s; sq[threadIdx.x] = q;
    __syncthreads();
    for (int o = 128; o > 0; o >>= 1) {
        if (threadIdx.x < o) { ss[threadIdx.x] += ss[threadIdx.x+o]; sq[threadIdx.x] += sq[threadIdx.x+o]; }
        __syncthreads();
    }
    if (threadIdx.x == 0) {
        g_ps[b * 8 + part] = ss[0];
        g_pq[b * 8 + part] = sq[0];
    }
}

// stage 2: one block, 64 threads, fixed summation order (deterministic)
__global__ void ln_stats2_kernel() {
    int b = threadIdx.x;
    if (b < BSZ) {
        float s = 0.f, q = 0.f;
        for (int i = 0; i < 8; i++) { s += g_ps[b*8+i]; q += g_pq[b*8+i]; }
        float mu  = s / (float)NT_;
        float var = q / (float)NT_ - mu * mu;
        g_mu[b] = mu;
        g_rstd[b] = rsqrtf(var + 1e-5f);
    }
}

// x_ln -> h/l bf16 only (no fp32 mirror)
__global__ void ln_apply_kernel(const float* __restrict__ x,
                                const float* __restrict__ lw,
                                const float* __restrict__ lb) {
    int i4 = blockIdx.x * 256 + threadIdx.x;
    int base = i4 * 4;
    int b  = base / NT_;
    int nt4 = (base % NT_) / 4;
    float mu = g_mu[b], rs = g_rstd[b];
    float4 v = ((const float4*)x)[i4];
    float4 w = ((const float4*)lw)[nt4];
    float4 bb = ((const float4*)lb)[nt4];
    float4 o;
    o.x = (v.x - mu) * rs * w.x + bb.x;
    o.y = (v.y - mu) * rs * w.y + bb.y;
    o.z = (v.z - mu) * rs * w.z + bb.z;
    o.w = (v.w - mu) * rs * w.w + bb.w;
    split4_store(o, g_xlnh, g_xlnl, (long)base);
}

// BatchNorm stats stage 1: grid (NN_, 4); block (n, p) reduces batches
// [p*16, p*16+16) for node n.
__global__ void bn_stats1_kernel() {
    int n = blockIdx.x, part = blockIdx.y;
    float s = 0.f, q = 0.f;
    for (int i = threadIdx.x; i < (16*TT_)/4; i += 256) {
        int base = i * 4;
        int b = part * 16 + base / TT_;
        int t = base % TT_;
        float4 v = hl_load4(g_xlnh, g_xlnl, ((long)b * NN_ + n) * TT_ + t);
        s += v.x + v.y + v.z + v.w;
        q += v.x*v.x + v.y*v.y + v.z*v.z + v.w*v.w;
    }
    __shared__ float ss[256], sq[256];
    ss[threadIdx.x] = s; sq[threadIdx.x] = q;
    __syncthreads();
    for (int o = 128; o > 0; o >>= 1) {
        if (threadIdx.x < o) { ss[threadIdx.x] += ss[threadIdx.x+o]; sq[threadIdx.x] += sq[threadIdx.x+o]; }
        __syncthreads();
    }
    if (threadIdx.x == 0) {
        g_bps[n * 4 + part] = ss[0];
        g_bpq[n * 4 + part] = sq[0];
    }
}

// BatchNorm stats stage 2: one block, 256 threads, fixed summation order
__global__ void bn_stats2_kernel(const float* __restrict__ bg,
                                 const float* __restrict__ bb) {
    int n = threadIdx.x;
    float s = 0.f, q = 0.f;
    for (int i = 0; i < 4; i++) { s += g_bps[n*4+i]; q += g_bpq[n*4+i]; }
    float cnt  = (float)(BSZ * TT_);
    float mean = s / cnt;
    float var  = q / cnt - mean * mean;
    float sc   = bg[n] * rsqrtf(var + 1e-5f);
    g_bns[n] = sc;
    g_bnh[n] = bb[n] - mean * sc;
}

// x_bn -> cat slot 0 (bf16 h/l, ld KCAT) only (no fp32 mirror)
__global__ void bn_apply_kernel() {
    int i4 = blockIdx.x * 256 + threadIdx.x;
    int base = i4 * 4;
    int row = base / TT_;
    int col = base % TT_;
    int n = row & (NN_ - 1);
    float sc = g_bns[n], sh = g_bnh[n];
    float4 v = hl_load4(g_xlnh, g_xlnl, (long)base);
    float4 o;
    o.x = v.x * sc + sh; o.y = v.y * sc + sh;
    o.z = v.z * sc + sh; o.w = v.w * sc + sh;
    split4_store(o, g_cath, g_catl, (long)row * KCAT + col);
}

__global__ void convert_kernel(const float* __restrict__ src,
                               __nv_bfloat16* __restrict__ h,
                               __nv_bfloat16* __restrict__ l) {
    int i4 = blockIdx.x * 256 + threadIdx.x;
    float4 v = ((const float4*)src)[i4];
    split4_store(v, h, l, (long)i4 * 4);
}

// bitonic-sort top-k (R8/R12 proven)
__global__ void topk_kernel(const float* __restrict__ dis) {
    int row = blockIdx.x;
    int n = row & (NN_ - 1);
    int tid = threadIdx.x;
    __shared__ float raw[256], srt[256];
    float v = g_sc[(long)row * NN_ + tid];
    raw[tid] = v; srt[tid] = v;
    __syncthreads();
    for (unsigned k = 2; k <= 256; k <<= 1) {
        for (unsigned j = k >> 1; j > 0; j >>= 1) {
            unsigned ixj = tid ^ j;
            if (ixj > (unsigned)tid) {
                float a = srt[tid], b2 = srt[ixj];
                bool asc = ((tid & k) == 0);
                if ((a > b2) == asc) { srt[tid] = b2; srt[ixj] = a; }
            }
            __syncthreads();
        }
    }
    float kth = srt[256 - NMAX];
    __syncthreads();
    float a = (raw[tid] >= kth) ? raw[tid] : 0.f;
    a += dis[n * NN_ + tid];
    a = fmaxf(a, 0.f);
    srt[tid] = a;
    __syncthreads();
    for (int o = 128; o > 0; o >>= 1) {
        if (tid < o) srt[tid] += srt[tid + o];
        __syncthreads();
    }
    g_sc[(long)row * NN_ + tid] = a;
    if (tid == 0) g_dinv[row] = rsqrtf(srt[0] + 1e-10f);
}

// L = D^-1/2 A D^-1/2 -> bf16 h/l
__global__ void lscale_kernel() {
    int i4 = blockIdx.x * 256 + threadIdx.x;
    int base = i4 * 4;
    int b   = base / (NN_ * NN_);
    int rem = base % (NN_ * NN_);
    int n   = rem / NN_;
    int m   = rem % NN_;
    float dn = g_dinv[b * NN_ + n];
    const float* dm = &g_dinv[b * NN_ + m];
    float4 a = ((const float4*)g_sc)[i4];
    a.x *= dn * dm[0];
    a.y *= dn * dm[1];
    a.z *= dn * dm[2];
    a.w *= dn * dm[3];
    split4_store(a, g_sch, g_scl, (long)base);
}

// ======================= launch =======================
extern "C" void kernel_launch(void* const* d_in, const int* in_sizes, int n_in,
                              void* d_out, int out_size) {
    const float* x      = (const float*)d_in[0];
    const float* dis    = (const float*)d_in[1];
    const float* ln_w   = (const float*)d_in[2];
    const float* ln_b   = (const float*)d_in[3];
    const float* bn_g   = (const float*)d_in[4];
    const float* bn_b   = (const float*)d_in[5];
    const float* li_w   = (const float*)d_in[6];
    const float* li_b   = (const float*)d_in[7];
    const float* cheb_w = (const float*)d_in[8];
    const float* cheb_b = (const float*)d_in[9];
    float* out = (float*)d_out;

    __nv_bfloat16 *xlnh, *xlnl, *xph, *xpl, *sch, *scl, *cath, *catl;
    __nv_bfloat16 *liwh, *liwl, *chwh, *chwl;
    float *sc;
    cudaGetSymbolAddress((void**)&xlnh, g_xlnh);
    cudaGetSymbolAddress((void**)&xlnl, g_xlnl);
    cudaGetSymbolAddress((void**)&xph,  g_xph);
    cudaGetSymbolAddress((void**)&xpl,  g_xpl);
    cudaGetSymbolAddress((void**)&sch,  g_sch);
    cudaGetSymbolAddress((void**)&scl,  g_scl);
    cudaGetSymbolAddress((void**)&cath, g_cath);
    cudaGetSymbolAddress((void**)&catl, g_catl);
    cudaGetSymbolAddress((void**)&liwh, g_liwh);
    cudaGetSymbolAddress((void**)&liwl, g_liwl);
    cudaGetSymbolAddress((void**)&chwh, g_chwh);
    cudaGetSymbolAddress((void**)&chwl, g_chwl);
    cudaGetSymbolAddress((void**)&sc,   g_sc);

    cudaFuncSetAttribute(gemm_tc_kernel<true>,
                         cudaFuncAttributeMaxDynamicSharedMemorySize, SMEM_GEMM);
    cudaFuncSetAttribute(gemm_tc_kernel<false>,
                         cudaFuncAttributeMaxDynamicSharedMemorySize, SMEM_GEMM);

    // 1. LayerNorm (2-stage stats) -> xln h/l
    {
        dim3 g1(BSZ, 8, 1);
        ln_stats1_kernel<<<g1, 256>>>(x);
        ln_stats2_kernel<<<1, 64>>>();
    }
    ln_apply_kernel<<<BNT/4/256, 256>>>(x, ln_w, ln_b);

    // 2. BatchNorm (2-stage stats) -> cat slot0 h/l
    {
        dim3 g1(NN_, 4, 1);
        bn_stats1_kernel<<<g1, 256>>>();
        bn_stats2_kernel<<<1, NN_>>>(bn_g, bn_b);
    }
    bn_apply_kernel<<<BNT/4/256, 256>>>();

    // 3. weight conversion
    convert_kernel<<<(TT_*TT_)/4/256, 256>>>(li_w, liwh, liwl);
    convert_kernel<<<(KCAT*TT_)/4/256, 256>>>(cheb_w, chwh, chwl);

    // 4. xp = x_ln @ li_w^T + li_b  -> xp h/l
    {
        dim3 g(TT_/128, (BSZ*NN_)/128, 1);
        gemm_tc_kernel<true><<<g, 256, SMEM_GEMM>>>(
            xlnh, xlnl, liwh, liwl, 0, 0, li_b, 0, xph, xpl,
            TT_, TT_, TT_, TT_, 0, 0, 0, 0, 0, 1.f, 0.f, 0);
    }
    // 5. scores = xp @ xp^T  -> sc fp32
    {
        dim3 g(NN_/128, NN_/128, BSZ);
        gemm_tc_kernel<true><<<g, 256, SMEM_GEMM>>>(
            xph, xpl, xph, xpl, 0, 0, 0, sc, 0, 0,
            TT_, TT_, TT_, NN_, 0,
            (long)NT_, (long)NT_, (long)NN_*NN_, 0, 1.f, 0.f, 0);
    }
    // 6. top-k + dis prior + relu + degree
    topk_kernel<<<BSZ*NN_, 256>>>(dis);
    // 7. L -> sc h/l
    lscale_kernel<<<BNN/4/256, 256>>>();

    // 8. Tx1 = L @ Tx0 -> cat slot1 h/l
    {
        dim3 g(TT_/128, NN_/128, BSZ);
        gemm_tc_kernel<false><<<g, 256, SMEM_GEMM>>>(
            sch, scl, cath, catl, 0, 0, 0, 0, cath + TT_, catl + TT_,
            NN_, NN_, KCAT, KCAT, 0,
            (long)NN_*NN_, (long)NN_*KCAT, (long)NN_*KCAT, 0, 1.f, 0.f, 0);
    }
    // 9. Tx2 = 2*L @ Tx1 - Tx0 -> cat slot2 h/l  (D = cat slot0 h/l)
    {
        dim3 g(TT_/128, NN_/128, BSZ);
        gemm_tc_kernel<false><<<g, 256, SMEM_GEMM>>>(
            sch, scl, cath + TT_, catl + TT_, cath, catl, 0, 0,
            cath + 2*TT_, catl + 2*TT_,
            NN_, NN_, KCAT, KCAT, KCAT,
            (long)NN_*NN_, (long)NN_*KCAT, (long)NN_*KCAT, (long)NN_*KCAT,
            2.f, -1.f, 0);
    }
    // 10. out = relu(cat @ cheb_flat + cheb_b)
    {
        dim3 g(TT_/128, (BSZ*NN_)/128, 1);
        gemm_tc_kernel<false><<<g, 256, SMEM_GEMM>>>(
            cath, catl, chwh, chwl, 0, 0, cheb_b, out, 0, 0,
            KCAT, KCAT, TT_, TT_, 0, 0, 0, 0, 0, 1.f, 0.f, 1);
    }
}

// round 16
// speedup vs baseline: 1.1000x; 1.0885x over previous
#include <cuda_runtime.h>
#include <cuda_bf16.h>
#include <cstdint>

// Problem constants
#define BSZ 64
#define NN_ 256
#define TT_ 512
#define NT_ (NN_*TT_)          // 131072
#define BNT (BSZ*NN_*TT_)      // 8388608
#define BNN (BSZ*NN_*NN_)      // 4194304
#define NMAX 51                // 256/5
#define KCAT 1536              // 3*T concatenated Chebyshev inputs
#define CATN ((long)BSZ*NN_*KCAT)

// -------- scratch (device globals; no allocation allowed) --------
__device__ __align__(256) float g_sc [BNN];   // scores -> A (topk in place)
__device__ __align__(256) __nv_bfloat16 g_xlnh[BNT];
__device__ __align__(256) __nv_bfloat16 g_xlnl[BNT];
__device__ __align__(256) __nv_bfloat16 g_xph [BNT];
__device__ __align__(256) __nv_bfloat16 g_xpl [BNT];
__device__ __align__(256) __nv_bfloat16 g_sch [BNN];
__device__ __align__(256) __nv_bfloat16 g_scl [BNN];
__device__ __align__(256) __nv_bfloat16 g_cath[CATN];
__device__ __align__(256) __nv_bfloat16 g_catl[CATN];
__device__ __align__(256) __nv_bfloat16 g_liwh[TT_*TT_];
__device__ __align__(256) __nv_bfloat16 g_liwl[TT_*TT_];
__device__ __align__(256) __nv_bfloat16 g_chwh[KCAT*TT_];
__device__ __align__(256) __nv_bfloat16 g_chwl[KCAT*TT_];
__device__ float g_mu  [BSZ];
__device__ float g_rstd[BSZ];
__device__ float g_ps  [BSZ*8];
__device__ float g_pq  [BSZ*8];
__device__ float g_bps [NN_*4];
__device__ float g_bpq [NN_*4];
__device__ float g_bns [NN_];
__device__ float g_bnh [NN_];
__device__ __align__(256) float g_dinv[BSZ*NN_];

// ======================= helpers =======================
__device__ __forceinline__ uint32_t smem_u32(const void* p) {
    uint32_t a;
    asm("{ .reg .u64 t; cvta.to.shared.u64 t, %1; cvt.u32.u64 %0, t; }"
        : "=r"(a) : "l"(p));
    return a;
}
__device__ __forceinline__ void cpasync16(uint32_t dst, const void* src) {
    asm volatile("cp.async.cg.shared.global [%0], [%1], 16;"
                 :: "r"(dst), "l"(src) : "memory");
}
#define CP_COMMIT() asm volatile("cp.async.commit_group;" ::: "memory")
#define CP_WAIT0()  asm volatile("cp.async.wait_group 0;" ::: "memory")

__device__ __forceinline__ void ldsm_x4(uint32_t addr, uint32_t* r) {
    asm volatile("ldmatrix.sync.aligned.m8n8.x4.shared.b16 {%0,%1,%2,%3}, [%4];"
        : "=r"(r[0]), "=r"(r[1]), "=r"(r[2]), "=r"(r[3]) : "r"(addr));
}
__device__ __forceinline__ void ldsm_x4_t(uint32_t addr, uint32_t* r) {
    asm volatile("ldmatrix.sync.aligned.m8n8.x4.trans.shared.b16 {%0,%1,%2,%3}, [%4];"
        : "=r"(r[0]), "=r"(r[1]), "=r"(r[2]), "=r"(r[3]) : "r"(addr));
}
__device__ __forceinline__ void mma_bf16(float* c, const uint32_t* a,
                                         uint32_t b0, uint32_t b1) {
    asm volatile(
        "mma.sync.aligned.m16n8k16.row.col.f32.bf16.bf16.f32 "
        "{%0,%1,%2,%3}, {%4,%5,%6,%7}, {%8,%9}, {%0,%1,%2,%3};"
        : "+f"(c[0]), "+f"(c[1]), "+f"(c[2]), "+f"(c[3])
        : "r"(a[0]), "r"(a[1]), "r"(a[2]), "r"(a[3]), "r"(b0), "r"(b1));
}
__device__ __forceinline__ unsigned pack_bf2(float a, float b) {
    __nv_bfloat162 h = __floats2bfloat162_rn(a, b);
    return *reinterpret_cast<unsigned*>(&h);
}
__device__ __forceinline__ float2 bf2_to_f2(uint32_t u) {
    __nv_bfloat162 b = *reinterpret_cast<__nv_bfloat162*>(&u);
    return __bfloat1622float2(b);
}
__device__ __forceinline__ void split_bf(float v, float& hi, float& lo) {
    __nv_bfloat16 h = __float2bfloat16_rn(v);
    hi = __bfloat162float(h);
    lo = v - hi;
}
__device__ __forceinline__ void split4_store(float4 o, __nv_bfloat16* H,
                                             __nv_bfloat16* L, long idx) {
    float h0,h1,h2,h3,l0,l1,l2,l3;
    split_bf(o.x,h0,l0); split_bf(o.y,h1,l1);
    split_bf(o.z,h2,l2); split_bf(o.w,h3,l3);
    uint2 hh; hh.x = pack_bf2(h0,h1); hh.y = pack_bf2(h2,h3);
    uint2 ll; ll.x = pack_bf2(l0,l1); ll.y = pack_bf2(l2,l3);
    *(uint2*)(H + idx) = hh;
    *(uint2*)(L + idx) = ll;
}
// reconstruct 4 fp32 from h/l bf16 pair at idx (idx multiple of 4)
__device__ __forceinline__ float4 hl_load4(const __nv_bfloat16* H,
                                           const __nv_bfloat16* L, long idx) {
    uint2 hh = *(const uint2*)(H + idx);
    uint2 ll = *(const uint2*)(L + idx);
    float2 h01 = bf2_to_f2(hh.x), h23 = bf2_to_f2(hh.y);
    float2 l01 = bf2_to_f2(ll.x), l23 = bf2_to_f2(ll.y);
    return make_float4(h01.x + l01.x, h01.y + l01.y, h23.x + l23.x, h23.y + l23.y);
}

// ======================= GEMM (bf16 3-product, cp.async + ldmatrix) ==========
// C = alpha*A@op(B) + beta*(Dh+Dl) (+bias) (+relu); optional split outputs Ch/Cl.
// A (hi/lo bf16): MxK row-major. B: TRANSB ? NxK row-major : KxN row-major.
// CTA tile 128x128, K-chunk 32 (R8 layout), 2-stage pipeline, ONE sync per chunk
// (16 syncs total at K=512). 88KB dynamic smem (opt-in).
// smem per buffer: A 128 rows x 176B ([hi k0-31 64B][lo 64B][pad 48B]);
//   TRANSB B: same layout (128 n-rows); NN B: 32 k-rows x 528B ([hi 256B][lo 256B][pad]).
#define ATILE 22528
#define BUFSZ 45056
#define SMEM_GEMM (2*BUFSZ)    // 90112, opt-in

template<bool TRANSB>
__global__ __launch_bounds__(256, 2)
void gemm_tc_kernel(const __nv_bfloat16* __restrict__ Ahg, const __nv_bfloat16* __restrict__ Alg,
                    const __nv_bfloat16* __restrict__ Bhg, const __nv_bfloat16* __restrict__ Blg,
                    const __nv_bfloat16* __restrict__ Dh, const __nv_bfloat16* __restrict__ Dl,
                    const float* __restrict__ bias,
                    float* __restrict__ C,
                    __nv_bfloat16* __restrict__ Ch, __nv_bfloat16* __restrict__ Cl,
                    int Kd, int ldA, int ldB, int ldC, int ldD,
                    long sA, long sB, long sC, long sD,
                    float alpha, float beta, int relu) {
    extern __shared__ __align__(128) char smem[];
    uint32_t sb = smem_u32(smem);

    int tid = threadIdx.x, lane = tid & 31, warp = tid >> 5;
    int z = blockIdx.z;
    Ahg += (long)z * sA; Alg += (long)z * sA;
    Bhg += (long)z * sB; Blg += (long)z * sB;
    if (C)  C  += (long)z * sC;
    if (Ch) { Ch += (long)z * sC; Cl += (long)z * sC; }
    if (Dh) { Dh += (long)z * sD; Dl += (long)z * sD; }
    int rowBase = blockIdx.y * 128;
    int colBase = blockIdx.x * 128;

    int g = lane >> 2, t4 = lane & 3;
    int mW = (warp >> 1) * 32, nW = (warp & 1) * 64;

    // per-lane ldmatrix byte offsets (R8-proven layouts)
    uint32_t aoff = (uint32_t)((mW + (lane & 15)) * 176 + ((lane >> 4) << 4));
    uint32_t boff;
    if (TRANSB)
        boff = (uint32_t)((nW + (lane & 7) + ((lane >> 4) << 3)) * 176
                          + (((lane >> 3) & 1) << 4));
    else
        boff = (uint32_t)(((lane & 7) + (((lane >> 3) & 1) << 3)) * 528
                          + (nW + ((lane >> 4) << 3)) * 2);

    float acc[2][8][4];
#pragma unroll
    for (int t = 0; t < 2; t++)
#pragma unroll
        for (int j = 0; j < 8; j++)
#pragma unroll
            for (int c = 0; c < 4; c++) acc[t][j][c] = 0.f;

    int nCh = Kd >> 5;

    auto FILL = [&](int ch, int buf) {
        uint32_t ab = sb + buf * BUFSZ;
        uint32_t bb = ab + ATILE;
        int kt = ch << 5;
#pragma unroll
        for (int i = 0; i < 4; i++) {
            int idx = tid + (i << 8);
            int r = idx >> 3, c = idx & 7;                   // c<4 hi, else lo
            const __nv_bfloat16* src = (c < 4 ? Ahg : Alg)
                + (long)(rowBase + r) * ldA + kt + (c & 3) * 8;
            cpasync16(ab + r * 176 + c * 16, src);
        }
        if (TRANSB) {
#pragma unroll
            for (int i = 0; i < 4; i++) {
                int idx = tid + (i << 8);
                int r = idx >> 3, c = idx & 7;
                const __nv_bfloat16* src = (c < 4 ? Bhg : Blg)
                    + (long)(colBase + r) * ldB + kt + (c & 3) * 8;
                cpasync16(bb + r * 176 + c * 16, src);
            }
        } else {
#pragma unroll
            for (int i = 0; i < 4; i++) {
                int idx = tid + (i << 8);
                int k = idx >> 5, c = idx & 31;              // c<16 hi, else lo
                const __nv_bfloat16* src = (c < 16 ? Bhg : Blg)
                    + (long)(kt + k) * ldB + colBase + (c & 15) * 8;
                cpasync16(bb + k * 528 + c * 16, src);
            }
        }
    };

    auto MMASTEP = [&](int buf) {
        uint32_t ab = sb + buf * BUFSZ, bb = ab + ATILE;
#pragma unroll
        for (int ks = 0; ks < 2; ks++) {
            uint32_t ahf[2][4], alf[2][4];
            ldsm_x4(ab + aoff + ks * 32,        ahf[0]);
            ldsm_x4(ab + aoff + 2816 + ks * 32, ahf[1]);
            ldsm_x4(ab + aoff + 64 + ks * 32,        alf[0]);
            ldsm_x4(ab + aoff + 64 + 2816 + ks * 32, alf[1]);
#pragma unroll
            for (int jt = 0; jt < 4; jt++) {
                uint32_t bh[4], bl[4];
                if (TRANSB) {
                    ldsm_x4(bb + boff + jt * 2816 + ks * 32,      bh);
                    ldsm_x4(bb + boff + jt * 2816 + ks * 32 + 64, bl);
                } else {
                    ldsm_x4_t(bb + boff + ks * 8448 + jt * 32,       bh);
                    ldsm_x4_t(bb + boff + ks * 8448 + jt * 32 + 256, bl);
                }
#pragma unroll
                for (int j2 = 0; j2 < 2; j2++) {
                    int j = jt * 2 + j2;
#pragma unroll
                    for (int mt = 0; mt < 2; mt++) {
                        mma_bf16(acc[mt][j], ahf[mt], bh[j2*2], bh[j2*2+1]);
                        mma_bf16(acc[mt][j], alf[mt], bh[j2*2], bh[j2*2+1]);
                        mma_bf16(acc[mt][j], ahf[mt], bl[j2*2], bl[j2*2+1]);
                    }
                }
            }
        }
    };

    // Single-sync pipeline (R12 proven), k32 chunks:
    //   wait fill(c) -> sync -> issue FILL(c+1) -> MMASTEP(c)
    FILL(0, 0); CP_COMMIT();
    for (int c = 0; c < nCh; c++) {
        CP_WAIT0();
        __syncthreads();
        if (c + 1 < nCh) { FILL(c + 1, (c + 1) & 1); CP_COMMIT(); }
        MMASTEP(c & 1);
    }

    // ---- epilogue ----
#pragma unroll
    for (int mt = 0; mt < 2; mt++) {
#pragma unroll
        for (int j = 0; j < 8; j++) {
            int c0 = colBase + nW + j * 8 + t4 * 2;
            float bs0 = 0.f, bs1 = 0.f;
            if (bias) { bs0 = bias[c0]; bs1 = bias[c0 + 1]; }
#pragma unroll
            for (int rr = 0; rr < 2; rr++) {
                int r = rowBase + mW + mt * 16 + g + rr * 8;
                float v0 = alpha * acc[mt][j][rr * 2 + 0];
                float v1 = alpha * acc[mt][j][rr * 2 + 1];
                if (Dh) {
                    long db = (long)r * ldD + c0;
                    float2 dh = bf2_to_f2(*(const uint32_t*)(Dh + db));
                    float2 dl = bf2_to_f2(*(const uint32_t*)(Dl + db));
                    v0 += beta * (dh.x + dl.x);
                    v1 += beta * (dh.y + dl.y);
                }
                v0 += bs0; v1 += bs1;
                if (relu) { v0 = fmaxf(v0, 0.f); v1 = fmaxf(v1, 0.f); }
                long cb = (long)r * ldC + c0;
                if (C) { *(float2*)(C + cb) = make_float2(v0, v1); }
                if (Ch) {
                    float h0,l0,h1,l1;
                    split_bf(v0, h0, l0); split_bf(v1, h1, l1);
                    *(uint32_t*)(Ch + cb) = pack_bf2(h0, h1);
                    *(uint32_t*)(Cl + cb) = pack_bf2(l0, l1);
                }
            }
        }
    }
}

// ======================= elementwise kernels =======================
// LayerNorm stats, stage 1: grid (BSZ, 8), each block reduces NT_/8 elements.
__global__ void ln_stats1_kernel(const float* __restrict__ x) {
    int b = blockIdx.x, part = blockIdx.y;
    const float4* xb = (const float4*)(x + (long)b * NT_ + part * (NT_/8));
    float s = 0.f, q = 0.f;
    for (int i = threadIdx.x; i < NT_/8/4; i += 256) {
        float4 v = xb[i];
        s += v.x + v.y + v.z + v.w;
        q += v.x*v.x + v.y*v.y + v.z*v.z + v.w*v.w;
    }
    __shared__ float ss[256], sq[256];
    ss[threadIdx.x] = s; sq[threadIdx.x] = q;
    __syncthreads();
    for (int o = 128; o > 0; o >>= 1) {
        if (threadIdx.x < o) { ss[threadIdx.x] += ss[threadIdx.x+o]; sq[threadIdx.x] += sq[threadIdx.x+o]; }
        __syncthreads();
    }
    if (threadIdx.x == 0) {
        g_ps[b * 8 + part] = ss[0];
        g_pq[b * 8 + part] = sq[0];
    }
}

// stage 2: one block, 64 threads, fixed summation order (deterministic)
__global__ void ln_stats2_kernel() {
    int b = threadIdx.x;
    if (b < BSZ) {
        float s = 0.f, q = 0.f;
        for (int i = 0; i < 8; i++) { s += g_ps[b*8+i]; q += g_pq[b*8+i]; }
        float mu  = s / (float)NT_;
        float var = q / (float)NT_ - mu * mu;
        g_mu[b] = mu;
        g_rstd[b] = rsqrtf(var + 1e-5f);
    }
}

// x_ln -> h/l bf16 only (no fp32 mirror)
__global__ void ln_apply_kernel(const float* __restrict__ x,
                                const float* __restrict__ lw,
                                const float* __restrict__ lb) {
    int i4 = blockIdx.x * 256 + threadIdx.x;
    int base = i4 * 4;
    int b  = base / NT_;
    int nt4 = (base % NT_) / 4;
    float mu = g_mu[b], rs = g_rstd[b];
    float4 v = ((const float4*)x)[i4];
    float4 w = ((const float4*)lw)[nt4];
    float4 bb = ((const float4*)lb)[nt4];
    float4 o;
    o.x = (v.x - mu) * rs * w.x + bb.x;
    o.y = (v.y - mu) * rs * w.y + bb.y;
    o.z = (v.z - mu) * rs * w.z + bb.z;
    o.w = (v.w - mu) * rs * w.w + bb.w;
    split4_store(o, g_xlnh, g_xlnl, (long)base);
}

// BatchNorm stats stage 1: grid (NN_, 4); block (n, p) reduces batches
// [p*16, p*16+16) for node n.
__global__ void bn_stats1_kernel() {
    int n = blockIdx.x, part = blockIdx.y;
    float s = 0.f, q = 0.f;
    for (int i = threadIdx.x; i < (16*TT_)/4; i += 256) {
        int base = i * 4;
        int b = part * 16 + base / TT_;
        int t = base % TT_;
        float4 v = hl_load4(g_xlnh, g_xlnl, ((long)b * NN_ + n) * TT_ + t);
        s += v.x + v.y + v.z + v.w;
        q += v.x*v.x + v.y*v.y + v.z*v.z + v.w*v.w;
    }
    __shared__ float ss[256], sq[256];
    ss[threadIdx.x] = s; sq[threadIdx.x] = q;
    __syncthreads();
    for (int o = 128; o > 0; o >>= 1) {
        if (threadIdx.x < o) { ss[threadIdx.x] += ss[threadIdx.x+o]; sq[threadIdx.x] += sq[threadIdx.x+o]; }
        __syncthreads();
    }
    if (threadIdx.x == 0) {
        g_bps[n * 4 + part] = ss[0];
        g_bpq[n * 4 + part] = sq[0];
    }
}

// BatchNorm stats stage 2: one block, 256 threads, fixed summation order
__global__ void bn_stats2_kernel(const float* __restrict__ bg,
                                 const float* __restrict__ bb) {
    int n = threadIdx.x;
    float s = 0.f, q = 0.f;
    for (int i = 0; i < 4; i++) { s += g_bps[n*4+i]; q += g_bpq[n*4+i]; }
    float cnt  = (float)(BSZ * TT_);
    float mean = s / cnt;
    float var  = q / cnt - mean * mean;
    float sc   = bg[n] * rsqrtf(var + 1e-5f);
    g_bns[n] = sc;
    g_bnh[n] = bb[n] - mean * sc;
}

// x_bn -> cat slot 0 (bf16 h/l, ld KCAT) only (no fp32 mirror)
__global__ void bn_apply_kernel() {
    int i4 = blockIdx.x * 256 + threadIdx.x;
    int base = i4 * 4;
    int row = base / TT_;
    int col = base % TT_;
    int n = row & (NN_ - 1);
    float sc = g_bns[n], sh = g_bnh[n];
    float4 v = hl_load4(g_xlnh, g_xlnl, (long)base);
    float4 o;
    o.x = v.x * sc + sh; o.y = v.y * sc + sh;
    o.z = v.z * sc + sh; o.w = v.w * sc + sh;
    split4_store(o, g_cath, g_catl, (long)row * KCAT + col);
}

__global__ void convert_kernel(const float* __restrict__ src,
                               __nv_bfloat16* __restrict__ h,
                               __nv_bfloat16* __restrict__ l) {
    int i4 = blockIdx.x * 256 + threadIdx.x;
    float4 v = ((const float4*)src)[i4];
    split4_store(v, h, l, (long)i4 * 4);
}

// bitonic-sort top-k (R8/R12 proven)
__global__ void topk_kernel(const float* __restrict__ dis) {
    int row = blockIdx.x;
    int n = row & (NN_ - 1);
    int tid = threadIdx.x;
    __shared__ float raw[256], srt[256];
    float v = g_sc[(long)row * NN_ + tid];
    raw[tid] = v; srt[tid] = v;
    __syncthreads();
    for (unsigned k = 2; k <= 256; k <<= 1) {
        for (unsigned j = k >> 1; j > 0; j >>= 1) {
            unsigned ixj = tid ^ j;
            if (ixj > (unsigned)tid) {
                float a = srt[tid], b2 = srt[ixj];
                bool asc = ((tid & k) == 0);
                if ((a > b2) == asc) { srt[tid] = b2; srt[ixj] = a; }
            }
            __syncthreads();
        }
    }
    float kth = srt[256 - NMAX];
    __syncthreads();
    float a = (raw[tid] >= kth) ? raw[tid] : 0.f;
    a += dis[n * NN_ + tid];
    a = fmaxf(a, 0.f);
    srt[tid] = a;
    __syncthreads();
    for (int o = 128; o > 0; o >>= 1) {
        if (tid < o) srt[tid] += srt[tid + o];
        __syncthreads();
    }
    g_sc[(long)row * NN_ + tid] = a;
    if (tid == 0) g_dinv[row] = rsqrtf(srt[0] + 1e-10f);
}

// L = D^-1/2 A D^-1/2 -> bf16 h/l
__global__ void lscale_kernel() {
    int i4 = blockIdx.x * 256 + threadIdx.x;
    int base = i4 * 4;
    int b   = base / (NN_ * NN_);
    int rem = base % (NN_ * NN_);
    int n   = rem / NN_;
    int m   = rem % NN_;
    float dn = g_dinv[b * NN_ + n];
    const float* dm = &g_dinv[b * NN_ + m];
    float4 a = ((const float4*)g_sc)[i4];
    a.x *= dn * dm[0];
    a.y *= dn * dm[1];
    a.z *= dn * dm[2];
    a.w *= dn * dm[3];
    split4_store(a, g_sch, g_scl, (long)base);
}

// ======================= launch =======================
extern "C" void kernel_launch(void* const* d_in, const int* in_sizes, int n_in,
                              void* d_out, int out_size) {
    const float* x      = (const float*)d_in[0];
    const float* dis    = (const float*)d_in[1];
    const float* ln_w   = (const float*)d_in[2];
    const float* ln_b   = (const float*)d_in[3];
    const float* bn_g   = (const float*)d_in[4];
    const float* bn_b   = (const float*)d_in[5];
    const float* li_w   = (const float*)d_in[6];
    const float* li_b   = (const float*)d_in[7];
    const float* cheb_w = (const float*)d_in[8];
    const float* cheb_b = (const float*)d_in[9];
    float* out = (float*)d_out;

    __nv_bfloat16 *xlnh, *xlnl, *xph, *xpl, *sch, *scl, *cath, *catl;
    __nv_bfloat16 *liwh, *liwl, *chwh, *chwl;
    float *sc;
    cudaGetSymbolAddress((void**)&xlnh, g_xlnh);
    cudaGetSymbolAddress((void**)&xlnl, g_xlnl);
    cudaGetSymbolAddress((void**)&xph,  g_xph);
    cudaGetSymbolAddress((void**)&xpl,  g_xpl);
    cudaGetSymbolAddress((void**)&sch,  g_sch);
    cudaGetSymbolAddress((void**)&scl,  g_scl);
    cudaGetSymbolAddress((void**)&cath, g_cath);
    cudaGetSymbolAddress((void**)&catl, g_catl);
    cudaGetSymbolAddress((void**)&liwh, g_liwh);
    cudaGetSymbolAddress((void**)&liwl, g_liwl);
    cudaGetSymbolAddress((void**)&chwh, g_chwh);
    cudaGetSymbolAddress((void**)&chwl, g_chwl);
    cudaGetSymbolAddress((void**)&sc,   g_sc);

    cudaFuncSetAttribute(gemm_tc_kernel<true>,
                         cudaFuncAttributeMaxDynamicSharedMemorySize, SMEM_GEMM);
    cudaFuncSetAttribute(gemm_tc_kernel<false>,
                         cudaFuncAttributeMaxDynamicSharedMemorySize, SMEM_GEMM);

    // 1. LayerNorm (2-stage stats) -> xln h/l
    {
        dim3 g1(BSZ, 8, 1);
        ln_stats1_kernel<<<g1, 256>>>(x);
        ln_stats2_kernel<<<1, 64>>>();
    }
    ln_apply_kernel<<<BNT/4/256, 256>>>(x, ln_w, ln_b);

    // 2. BatchNorm (2-stage stats) -> cat slot0 h/l
    {
        dim3 g1(NN_, 4, 1);
        bn_stats1_kernel<<<g1, 256>>>();
        bn_stats2_kernel<<<1, NN_>>>(bn_g, bn_b);
    }
    bn_apply_kernel<<<BNT/4/256, 256>>>();

    // 3. weight conversion
    convert_kernel<<<(TT_*TT_)/4/256, 256>>>(li_w, liwh, liwl);
    convert_kernel<<<(KCAT*TT_)/4/256, 256>>>(cheb_w, chwh, chwl);

    // 4. xp = x_ln @ li_w^T + li_b  -> xp h/l
    {
        dim3 g(TT_/128, (BSZ*NN_)/128, 1);
        gemm_tc_kernel<true><<<g, 256, SMEM_GEMM>>>(
            xlnh, xlnl, liwh, liwl, 0, 0, li_b, 0, xph, xpl,
            TT_, TT_, TT_, TT_, 0, 0, 0, 0, 0, 1.f, 0.f, 0);
    }
    // 5. scores = xp @ xp^T  -> sc fp32
    {
        dim3 g(NN_/128, NN_/128, BSZ);
        gemm_tc_kernel<true><<<g, 256, SMEM_GEMM>>>(
            xph, xpl, xph, xpl, 0, 0, 0, sc, 0, 0,
            TT_, TT_, TT_, NN_, 0,
            (long)NT_, (long)NT_, (long)NN_*NN_, 0, 1.f, 0.f, 0);
    }
    // 6. top-k + dis prior + relu + degree
    topk_kernel<<<BSZ*NN_, 256>>>(dis);
    // 7. L -> sc h/l
    lscale_kernel<<<BNN/4/256, 256>>>();

    // 8. Tx1 = L @ Tx0 -> cat slot1 h/l
    {
        dim3 g(TT_/128, NN_/128, BSZ);
        gemm_tc_kernel<false><<<g, 256, SMEM_GEMM>>>(
            sch, scl, cath, catl, 0, 0, 0, 0, cath + TT_, catl + TT_,
            NN_, NN_, KCAT, KCAT, 0,
            (long)NN_*NN_, (long)NN_*KCAT, (long)NN_*KCAT, 0, 1.f, 0.f, 0);
    }
    // 9. Tx2 = 2*L @ Tx1 - Tx0 -> cat slot2 h/l  (D = cat slot0 h/l)
    {
        dim3 g(TT_/128, NN_/128, BSZ);
        gemm_tc_kernel<false><<<g, 256, SMEM_GEMM>>>(
            sch, scl, cath + TT_, catl + TT_, cath, catl, 0, 0,
            cath + 2*TT_, catl + 2*TT_,
            NN_, NN_, KCAT, KCAT, KCAT,
            (long)NN_*NN_, (long)NN_*KCAT, (long)NN_*KCAT, (long)NN_*KCAT,
            2.f, -1.f, 0);
    }
    // 10. out = relu(cat @ cheb_flat + cheb_b)
    {
        dim3 g(TT_/128, (BSZ*NN_)/128, 1);
        gemm_tc_kernel<false><<<g, 256, SMEM_GEMM>>>(
            cath, catl, chwh, chwl, 0, 0, cheb_b, out, 0, 0,
            KCAT, KCAT, TT_, TT_, 0, 0, 0, 0, 0, 1.f, 0.f, 1);
    }
}

// round 17
// speedup vs baseline: 1.1209x; 1.0190x over previous
#include <cuda_runtime.h>
#include <cuda_bf16.h>
#include <cstdint>

// Problem constants
#define BSZ 64
#define NN_ 256
#define TT_ 512
#define NT_ (NN_*TT_)          // 131072
#define BNT (BSZ*NN_*TT_)      // 8388608
#define BNN (BSZ*NN_*NN_)      // 4194304
#define NMAX 51                // 256/5
#define KCAT 1536              // 3*T concatenated Chebyshev inputs
#define CATN ((long)BSZ*NN_*KCAT)

// -------- scratch (device globals; no allocation allowed) --------
__device__ __align__(256) float g_sc [BNN];   // scores -> A (topk in place)
__device__ __align__(256) __nv_bfloat16 g_xlnh[BNT];
__device__ __align__(256) __nv_bfloat16 g_xlnl[BNT];
__device__ __align__(256) __nv_bfloat16 g_xph [BNT];
__device__ __align__(256) __nv_bfloat16 g_xpl [BNT];
__device__ __align__(256) __nv_bfloat16 g_sch [BNN];
__device__ __align__(256) __nv_bfloat16 g_scl [BNN];
__device__ __align__(256) __nv_bfloat16 g_cath[CATN];
__device__ __align__(256) __nv_bfloat16 g_catl[CATN];
__device__ __align__(256) __nv_bfloat16 g_liwh[TT_*TT_];
__device__ __align__(256) __nv_bfloat16 g_liwl[TT_*TT_];
__device__ __align__(256) __nv_bfloat16 g_chwh[KCAT*TT_];
__device__ __align__(256) __nv_bfloat16 g_chwl[KCAT*TT_];
__device__ float g_mu  [BSZ];
__device__ float g_rstd[BSZ];
__device__ float g_ps  [BSZ*8];
__device__ float g_pq  [BSZ*8];
__device__ float g_bps [NN_*4];
__device__ float g_bpq [NN_*4];
__device__ float g_bns [NN_];
__device__ float g_bnh [NN_];
__device__ __align__(256) float g_dinv[BSZ*NN_];

// ======================= helpers =======================
__device__ __forceinline__ uint32_t smem_u32(const void* p) {
    uint32_t a;
    asm("{ .reg .u64 t; cvta.to.shared.u64 t, %1; cvt.u32.u64 %0, t; }"
        : "=r"(a) : "l"(p));
    return a;
}
__device__ __forceinline__ void cpasync16(uint32_t dst, const void* src) {
    asm volatile("cp.async.cg.shared.global [%0], [%1], 16;"
                 :: "r"(dst), "l"(src) : "memory");
}
#define CP_COMMIT() asm volatile("cp.async.commit_group;" ::: "memory")
#define CP_WAIT0()  asm volatile("cp.async.wait_group 0;" ::: "memory")

__device__ __forceinline__ void ldsm_x4(uint32_t addr, uint32_t* r) {
    asm volatile("ldmatrix.sync.aligned.m8n8.x4.shared.b16 {%0,%1,%2,%3}, [%4];"
        : "=r"(r[0]), "=r"(r[1]), "=r"(r[2]), "=r"(r[3]) : "r"(addr));
}
__device__ __forceinline__ void ldsm_x4_t(uint32_t addr, uint32_t* r) {
    asm volatile("ldmatrix.sync.aligned.m8n8.x4.trans.shared.b16 {%0,%1,%2,%3}, [%4];"
        : "=r"(r[0]), "=r"(r[1]), "=r"(r[2]), "=r"(r[3]) : "r"(addr));
}
__device__ __forceinline__ void mma_bf16(float* c, const uint32_t* a,
                                         uint32_t b0, uint32_t b1) {
    asm volatile(
        "mma.sync.aligned.m16n8k16.row.col.f32.bf16.bf16.f32 "
        "{%0,%1,%2,%3}, {%4,%5,%6,%7}, {%8,%9}, {%0,%1,%2,%3};"
        : "+f"(c[0]), "+f"(c[1]), "+f"(c[2]), "+f"(c[3])
        : "r"(a[0]), "r"(a[1]), "r"(a[2]), "r"(a[3]), "r"(b0), "r"(b1));
}
__device__ __forceinline__ unsigned pack_bf2(float a, float b) {
    __nv_bfloat162 h = __floats2bfloat162_rn(a, b);
    return *reinterpret_cast<unsigned*>(&h);
}
__device__ __forceinline__ float2 bf2_to_f2(uint32_t u) {
    __nv_bfloat162 b = *reinterpret_cast<__nv_bfloat162*>(&u);
    return __bfloat1622float2(b);
}
__device__ __forceinline__ void split_bf(float v, float& hi, float& lo) {
    __nv_bfloat16 h = __float2bfloat16_rn(v);
    hi = __bfloat162float(h);
    lo = v - hi;
}
__device__ __forceinline__ void split4_store(float4 o, __nv_bfloat16* H,
                                             __nv_bfloat16* L, long idx) {
    float h0,h1,h2,h3,l0,l1,l2,l3;
    split_bf(o.x,h0,l0); split_bf(o.y,h1,l1);
    split_bf(o.z,h2,l2); split_bf(o.w,h3,l3);
    uint2 hh; hh.x = pack_bf2(h0,h1); hh.y = pack_bf2(h2,h3);
    uint2 ll; ll.x = pack_bf2(l0,l1); ll.y = pack_bf2(l2,l3);
    *(uint2*)(H + idx) = hh;
    *(uint2*)(L + idx) = ll;
}
// reconstruct 4 fp32 from h/l bf16 pair at idx (idx multiple of 4)
__device__ __forceinline__ float4 hl_load4(const __nv_bfloat16* H,
                                           const __nv_bfloat16* L, long idx) {
    uint2 hh = *(const uint2*)(H + idx);
    uint2 ll = *(const uint2*)(L + idx);
    float2 h01 = bf2_to_f2(hh.x), h23 = bf2_to_f2(hh.y);
    float2 l01 = bf2_to_f2(ll.x), l23 = bf2_to_f2(ll.y);
    return make_float4(h01.x + l01.x, h01.y + l01.y, h23.x + l23.x, h23.y + l23.y);
}

// ======================= GEMM (bf16 3-product, cp.async + ldmatrix) ==========
// Byte-identical to R16 (proven 601us): CTA tile 128x128, K-chunk 32,
// 2-stage pipeline, ONE sync per chunk (16 syncs at K=512). 88KB smem opt-in.
#define ATILE 22528
#define BUFSZ 45056
#define SMEM_GEMM (2*BUFSZ)    // 90112, opt-in

template<bool TRANSB>
__global__ __launch_bounds__(256, 2)
void gemm_tc_kernel(const __nv_bfloat16* __restrict__ Ahg, const __nv_bfloat16* __restrict__ Alg,
                    const __nv_bfloat16* __restrict__ Bhg, const __nv_bfloat16* __restrict__ Blg,
                    const __nv_bfloat16* __restrict__ Dh, const __nv_bfloat16* __restrict__ Dl,
                    const float* __restrict__ bias,
                    float* __restrict__ C,
                    __nv_bfloat16* __restrict__ Ch, __nv_bfloat16* __restrict__ Cl,
                    int Kd, int ldA, int ldB, int ldC, int ldD,
                    long sA, long sB, long sC, long sD,
                    float alpha, float beta, int relu) {
    extern __shared__ __align__(128) char smem[];
    uint32_t sb = smem_u32(smem);

    int tid = threadIdx.x, lane = tid & 31, warp = tid >> 5;
    int z = blockIdx.z;
    Ahg += (long)z * sA; Alg += (long)z * sA;
    Bhg += (long)z * sB; Blg += (long)z * sB;
    if (C)  C  += (long)z * sC;
    if (Ch) { Ch += (long)z * sC; Cl += (long)z * sC; }
    if (Dh) { Dh += (long)z * sD; Dl += (long)z * sD; }
    int rowBase = blockIdx.y * 128;
    int colBase = blockIdx.x * 128;

    int g = lane >> 2, t4 = lane & 3;
    int mW = (warp >> 1) * 32, nW = (warp & 1) * 64;

    uint32_t aoff = (uint32_t)((mW + (lane & 15)) * 176 + ((lane >> 4) << 4));
    uint32_t boff;
    if (TRANSB)
        boff = (uint32_t)((nW + (lane & 7) + ((lane >> 4) << 3)) * 176
                          + (((lane >> 3) & 1) << 4));
    else
        boff = (uint32_t)(((lane & 7) + (((lane >> 3) & 1) << 3)) * 528
                          + (nW + ((lane >> 4) << 3)) * 2);

    float acc[2][8][4];
#pragma unroll
    for (int t = 0; t < 2; t++)
#pragma unroll
        for (int j = 0; j < 8; j++)
#pragma unroll
            for (int c = 0; c < 4; c++) acc[t][j][c] = 0.f;

    int nCh = Kd >> 5;

    auto FILL = [&](int ch, int buf) {
        uint32_t ab = sb + buf * BUFSZ;
        uint32_t bb = ab + ATILE;
        int kt = ch << 5;
#pragma unroll
        for (int i = 0; i < 4; i++) {
            int idx = tid + (i << 8);
            int r = idx >> 3, c = idx & 7;                   // c<4 hi, else lo
            const __nv_bfloat16* src = (c < 4 ? Ahg : Alg)
                + (long)(rowBase + r) * ldA + kt + (c & 3) * 8;
            cpasync16(ab + r * 176 + c * 16, src);
        }
        if (TRANSB) {
#pragma unroll
            for (int i = 0; i < 4; i++) {
                int idx = tid + (i << 8);
                int r = idx >> 3, c = idx & 7;
                const __nv_bfloat16* src = (c < 4 ? Bhg : Blg)
                    + (long)(colBase + r) * ldB + kt + (c & 3) * 8;
                cpasync16(bb + r * 176 + c * 16, src);
            }
        } else {
#pragma unroll
            for (int i = 0; i < 4; i++) {
                int idx = tid + (i << 8);
                int k = idx >> 5, c = idx & 31;              // c<16 hi, else lo
                const __nv_bfloat16* src = (c < 16 ? Bhg : Blg)
                    + (long)(kt + k) * ldB + colBase + (c & 15) * 8;
                cpasync16(bb + k * 528 + c * 16, src);
            }
        }
    };

    auto MMASTEP = [&](int buf) {
        uint32_t ab = sb + buf * BUFSZ, bb = ab + ATILE;
#pragma unroll
        for (int ks = 0; ks < 2; ks++) {
            uint32_t ahf[2][4], alf[2][4];
            ldsm_x4(ab + aoff + ks * 32,        ahf[0]);
            ldsm_x4(ab + aoff + 2816 + ks * 32, ahf[1]);
            ldsm_x4(ab + aoff + 64 + ks * 32,        alf[0]);
            ldsm_x4(ab + aoff + 64 + 2816 + ks * 32, alf[1]);
#pragma unroll
            for (int jt = 0; jt < 4; jt++) {
                uint32_t bh[4], bl[4];
                if (TRANSB) {
                    ldsm_x4(bb + boff + jt * 2816 + ks * 32,      bh);
                    ldsm_x4(bb + boff + jt * 2816 + ks * 32 + 64, bl);
                } else {
                    ldsm_x4_t(bb + boff + ks * 8448 + jt * 32,       bh);
                    ldsm_x4_t(bb + boff + ks * 8448 + jt * 32 + 256, bl);
                }
#pragma unroll
                for (int j2 = 0; j2 < 2; j2++) {
                    int j = jt * 2 + j2;
#pragma unroll
                    for (int mt = 0; mt < 2; mt++) {
                        mma_bf16(acc[mt][j], ahf[mt], bh[j2*2], bh[j2*2+1]);
                        mma_bf16(acc[mt][j], alf[mt], bh[j2*2], bh[j2*2+1]);
                        mma_bf16(acc[mt][j], ahf[mt], bl[j2*2], bl[j2*2+1]);
                    }
                }
            }
        }
    };

    FILL(0, 0); CP_COMMIT();
    for (int c = 0; c < nCh; c++) {
        CP_WAIT0();
        __syncthreads();
        if (c + 1 < nCh) { FILL(c + 1, (c + 1) & 1); CP_COMMIT(); }
        MMASTEP(c & 1);
    }

    // ---- epilogue ----
#pragma unroll
    for (int mt = 0; mt < 2; mt++) {
#pragma unroll
        for (int j = 0; j < 8; j++) {
            int c0 = colBase + nW + j * 8 + t4 * 2;
            float bs0 = 0.f, bs1 = 0.f;
            if (bias) { bs0 = bias[c0]; bs1 = bias[c0 + 1]; }
#pragma unroll
            for (int rr = 0; rr < 2; rr++) {
                int r = rowBase + mW + mt * 16 + g + rr * 8;
                float v0 = alpha * acc[mt][j][rr * 2 + 0];
                float v1 = alpha * acc[mt][j][rr * 2 + 1];
                if (Dh) {
                    long db = (long)r * ldD + c0;
                    float2 dh = bf2_to_f2(*(const uint32_t*)(Dh + db));
                    float2 dl = bf2_to_f2(*(const uint32_t*)(Dl + db));
                    v0 += beta * (dh.x + dl.x);
                    v1 += beta * (dh.y + dl.y);
                }
                v0 += bs0; v1 += bs1;
                if (relu) { v0 = fmaxf(v0, 0.f); v1 = fmaxf(v1, 0.f); }
                long cb = (long)r * ldC + c0;
                if (C) { *(float2*)(C + cb) = make_float2(v0, v1); }
                if (Ch) {
                    float h0,l0,h1,l1;
                    split_bf(v0, h0, l0); split_bf(v1, h1, l1);
                    *(uint32_t*)(Ch + cb) = pack_bf2(h0, h1);
                    *(uint32_t*)(Cl + cb) = pack_bf2(l0, l1);
                }
            }
        }
    }
}

// ======================= elementwise kernels =======================
__global__ void ln_stats1_kernel(const float* __restrict__ x) {
    int b = blockIdx.x, part = blockIdx.y;
    const float4* xb = (const float4*)(x + (long)b * NT_ + part * (NT_/8));
    float s = 0.f, q = 0.f;
    for (int i = threadIdx.x; i < NT_/8/4; i += 256) {
        float4 v = xb[i];
        s += v.x + v.y + v.z + v.w;
        q += v.x*v.x + v.y*v.y + v.z*v.z + v.w*v.w;
    }
    __shared__ float ss[256], sq[256];
    ss[threadIdx.x] = s; sq[threadIdx.x] = q;
    __syncthreads();
    for (int o = 128; o > 0; o >>= 1) {
        if (threadIdx.x < o) { ss[threadIdx.x] += ss[threadIdx.x+o]; sq[threadIdx.x] += sq[threadIdx.x+o]; }
        __syncthreads();
    }
    if (threadIdx.x == 0) {
        g_ps[b * 8 + part] = ss[0];
        g_pq[b * 8 + part] = sq[0];
    }
}

__global__ void ln_stats2_kernel() {
    int b = threadIdx.x;
    if (b < BSZ) {
        float s = 0.f, q = 0.f;
        for (int i = 0; i < 8; i++) { s += g_ps[b*8+i]; q += g_pq[b*8+i]; }
        float mu  = s / (float)NT_;
        float var = q / (float)NT_ - mu * mu;
        g_mu[b] = mu;
        g_rstd[b] = rsqrtf(var + 1e-5f);
    }
}

__global__ void ln_apply_kernel(const float* __restrict__ x,
                                const float* __restrict__ lw,
                                const float* __restrict__ lb) {
    int i4 = blockIdx.x * 256 + threadIdx.x;
    int base = i4 * 4;
    int b  = base / NT_;
    int nt4 = (base % NT_) / 4;
    float mu = g_mu[b], rs = g_rstd[b];
    float4 v = ((const float4*)x)[i4];
    float4 w = ((const float4*)lw)[nt4];
    float4 bb = ((const float4*)lb)[nt4];
    float4 o;
    o.x = (v.x - mu) * rs * w.x + bb.x;
    o.y = (v.y - mu) * rs * w.y + bb.y;
    o.z = (v.z - mu) * rs * w.z + bb.z;
    o.w = (v.w - mu) * rs * w.w + bb.w;
    split4_store(o, g_xlnh, g_xlnl, (long)base);
}

__global__ void bn_stats1_kernel() {
    int n = blockIdx.x, part = blockIdx.y;
    float s = 0.f, q = 0.f;
    for (int i = threadIdx.x; i < (16*TT_)/4; i += 256) {
        int base = i * 4;
        int b = part * 16 + base / TT_;
        int t = base % TT_;
        float4 v = hl_load4(g_xlnh, g_xlnl, ((long)b * NN_ + n) * TT_ + t);
        s += v.x + v.y + v.z + v.w;
        q += v.x*v.x + v.y*v.y + v.z*v.z + v.w*v.w;
    }
    __shared__ float ss[256], sq[256];
    ss[threadIdx.x] = s; sq[threadIdx.x] = q;
    __syncthreads();
    for (int o = 128; o > 0; o >>= 1) {
        if (threadIdx.x < o) { ss[threadIdx.x] += ss[threadIdx.x+o]; sq[threadIdx.x] += sq[threadIdx.x+o]; }
        __syncthreads();
    }
    if (threadIdx.x == 0) {
        g_bps[n * 4 + part] = ss[0];
        g_bpq[n * 4 + part] = sq[0];
    }
}

__global__ void bn_stats2_kernel(const float* __restrict__ bg,
                                 const float* __restrict__ bb) {
    int n = threadIdx.x;
    float s = 0.f, q = 0.f;
    for (int i = 0; i < 4; i++) { s += g_bps[n*4+i]; q += g_bpq[n*4+i]; }
    float cnt  = (float)(BSZ * TT_);
    float mean = s / cnt;
    float var  = q / cnt - mean * mean;
    float sc   = bg[n] * rsqrtf(var + 1e-5f);
    g_bns[n] = sc;
    g_bnh[n] = bb[n] - mean * sc;
}

__global__ void bn_apply_kernel() {
    int i4 = blockIdx.x * 256 + threadIdx.x;
    int base = i4 * 4;
    int row = base / TT_;
    int col = base % TT_;
    int n = row & (NN_ - 1);
    float sc = g_bns[n], sh = g_bnh[n];
    float4 v = hl_load4(g_xlnh, g_xlnl, (long)base);
    float4 o;
    o.x = v.x * sc + sh; o.y = v.y * sc + sh;
    o.z = v.z * sc + sh; o.w = v.w * sc + sh;
    split4_store(o, g_cath, g_catl, (long)row * KCAT + col);
}

// merged weight conversion: li_w (first LIW4 float4s) then cheb_w
#define LIW4 ((TT_*TT_)/4)
#define CHW4 ((KCAT*TT_)/4)
__global__ void convert_both_kernel(const float* __restrict__ liw,
                                    const float* __restrict__ chw) {
    int i4 = blockIdx.x * 256 + threadIdx.x;
    if (i4 < LIW4) {
        float4 v = ((const float4*)liw)[i4];
        split4_store(v, g_liwh, g_liwl, (long)i4 * 4);
    } else {
        int j4 = i4 - LIW4;
        float4 v = ((const float4*)chw)[j4];
        split4_store(v, g_chwh, g_chwl, (long)j4 * 4);
    }
}

// bitonic-sort top-k; final sum via warp shuffles (fewer barriers)
__global__ void topk_kernel(const float* __restrict__ dis) {
    int row = blockIdx.x;
    int n = row & (NN_ - 1);
    int tid = threadIdx.x;
    __shared__ float raw[256], srt[256];
    __shared__ float wsum[8];
    float v = g_sc[(long)row * NN_ + tid];
    raw[tid] = v; srt[tid] = v;
    __syncthreads();
    for (unsigned k = 2; k <= 256; k <<= 1) {
        for (unsigned j = k >> 1; j > 0; j >>= 1) {
            unsigned ixj = tid ^ j;
            if (ixj > (unsigned)tid) {
                float a = srt[tid], b2 = srt[ixj];
                bool asc = ((tid & k) == 0);
                if ((a > b2) == asc) { srt[tid] = b2; srt[ixj] = a; }
            }
            __syncthreads();
        }
    }
    float kth = srt[256 - NMAX];
    float a = (raw[tid] >= kth) ? raw[tid] : 0.f;
    a += dis[n * NN_ + tid];
    a = fmaxf(a, 0.f);
    g_sc[(long)row * NN_ + tid] = a;
    // warp-shuffle sum, then cross-warp via 8 partials
    float s = a;
#pragma unroll
    for (int o = 16; o > 0; o >>= 1)
        s += __shfl_xor_sync(0xFFFFFFFFu, s, o);
    if ((tid & 31) == 0) wsum[tid >> 5] = s;
    __syncthreads();
    if (tid == 0) {
        float tot = 0.f;
        for (int i = 0; i < 8; i++) tot += wsum[i];
        g_dinv[row] = rsqrtf(tot + 1e-10f);
    }
}

// L = D^-1/2 A D^-1/2 -> bf16 h/l
__global__ void lscale_kernel() {
    int i4 = blockIdx.x * 256 + threadIdx.x;
    int base = i4 * 4;
    int b   = base / (NN_ * NN_);
    int rem = base % (NN_ * NN_);
    int n   = rem / NN_;
    int m   = rem % NN_;
    float dn = g_dinv[b * NN_ + n];
    const float* dm = &g_dinv[b * NN_ + m];
    float4 a = ((const float4*)g_sc)[i4];
    a.x *= dn * dm[0];
    a.y *= dn * dm[1];
    a.z *= dn * dm[2];
    a.w *= dn * dm[3];
    split4_store(a, g_sch, g_scl, (long)base);
}

// ======================= launch =======================
extern "C" void kernel_launch(void* const* d_in, const int* in_sizes, int n_in,
                              void* d_out, int out_size) {
    const float* x      = (const float*)d_in[0];
    const float* dis    = (const float*)d_in[1];
    const float* ln_w   = (const float*)d_in[2];
    const float* ln_b   = (const float*)d_in[3];
    const float* bn_g   = (const float*)d_in[4];
    const float* bn_b   = (const float*)d_in[5];
    const float* li_w   = (const float*)d_in[6];
    const float* li_b   = (const float*)d_in[7];
    const float* cheb_w = (const float*)d_in[8];
    const float* cheb_b = (const float*)d_in[9];
    float* out = (float*)d_out;

    __nv_bfloat16 *xlnh, *xlnl, *xph, *xpl, *sch, *scl, *cath, *catl;
    __nv_bfloat16 *liwh, *liwl, *chwh, *chwl;
    float *sc;
    cudaGetSymbolAddress((void**)&xlnh, g_xlnh);
    cudaGetSymbolAddress((void**)&xlnl, g_xlnl);
    cudaGetSymbolAddress((void**)&xph,  g_xph);
    cudaGetSymbolAddress((void**)&xpl,  g_xpl);
    cudaGetSymbolAddress((void**)&sch,  g_sch);
    cudaGetSymbolAddress((void**)&scl,  g_scl);
    cudaGetSymbolAddress((void**)&cath, g_cath);
    cudaGetSymbolAddress((void**)&catl, g_catl);
    cudaGetSymbolAddress((void**)&liwh, g_liwh);
    cudaGetSymbolAddress((void**)&liwl, g_liwl);
    cudaGetSymbolAddress((void**)&chwh, g_chwh);
    cudaGetSymbolAddress((void**)&chwl, g_chwl);
    cudaGetSymbolAddress((void**)&sc,   g_sc);

    cudaFuncSetAttribute(gemm_tc_kernel<true>,
                         cudaFuncAttributeMaxDynamicSharedMemorySize, SMEM_GEMM);
    cudaFuncSetAttribute(gemm_tc_kernel<false>,
                         cudaFuncAttributeMaxDynamicSharedMemorySize, SMEM_GEMM);

    // 1. LayerNorm (2-stage stats) -> xln h/l
    {
        dim3 g1(BSZ, 8, 1);
        ln_stats1_kernel<<<g1, 256>>>(x);
        ln_stats2_kernel<<<1, 64>>>();
    }
    ln_apply_kernel<<<BNT/4/256, 256>>>(x, ln_w, ln_b);

    // 2. BatchNorm (2-stage stats) -> cat slot0 h/l
    {
        dim3 g1(NN_, 4, 1);
        bn_stats1_kernel<<<g1, 256>>>();
        bn_stats2_kernel<<<1, NN_>>>(bn_g, bn_b);
    }
    bn_apply_kernel<<<BNT/4/256, 256>>>();

    // 3. weight conversion (merged)
    convert_both_kernel<<<(LIW4 + CHW4)/256, 256>>>(li_w, cheb_w);

    // 4. xp = x_ln @ li_w^T + li_b  -> xp h/l
    {
        dim3 g(TT_/128, (BSZ*NN_)/128, 1);
        gemm_tc_kernel<true><<<g, 256, SMEM_GEMM>>>(
            xlnh, xlnl, liwh, liwl, 0, 0, li_b, 0, xph, xpl,
            TT_, TT_, TT_, TT_, 0, 0, 0, 0, 0, 1.f, 0.f, 0);
    }
    // 5. scores = xp @ xp^T  -> sc fp32
    {
        dim3 g(NN_/128, NN_/128, BSZ);
        gemm_tc_kernel<true><<<g, 256, SMEM_GEMM>>>(
            xph, xpl, xph, xpl, 0, 0, 0, sc, 0, 0,
            TT_, TT_, TT_, NN_, 0,
            (long)NT_, (long)NT_, (long)NN_*NN_, 0, 1.f, 0.f, 0);
    }
    // 6. top-k + dis prior + relu + degree
    topk_kernel<<<BSZ*NN_, 256>>>(dis);
    // 7. L -> sc h/l
    lscale_kernel<<<BNN/4/256, 256>>>();

    // 8. Tx1 = L @ Tx0 -> cat slot1 h/l
    {
        dim3 g(TT_/128, NN_/128, BSZ);
        gemm_tc_kernel<false><<<g, 256, SMEM_GEMM>>>(
            sch, scl, cath, catl, 0, 0, 0, 0, cath + TT_, catl + TT_,
            NN_, NN_, KCAT, KCAT, 0,
            (long)NN_*NN_, (long)NN_*KCAT, (long)NN_*KCAT, 0, 1.f, 0.f, 0);
    }
    // 9. Tx2 = 2*L @ Tx1 - Tx0 -> cat slot2 h/l  (D = cat slot0 h/l)
    {
        dim3 g(TT_/128, NN_/128, BSZ);
        gemm_tc_kernel<false><<<g, 256, SMEM_GEMM>>>(
            sch, scl, cath + TT_, catl + TT_, cath, catl, 0, 0,
            cath + 2*TT_, catl + 2*TT_,
            NN_, NN_, KCAT, KCAT, KCAT,
            (long)NN_*NN_, (long)NN_*KCAT, (long)NN_*KCAT, (long)NN_*KCAT,
            2.f, -1.f, 0);
    }
    // 10. out = relu(cat @ cheb_flat + cheb_b)
    {
        dim3 g(TT_/128, (BSZ*NN_)/128, 1);
        gemm_tc_kernel<false><<<g, 256, SMEM_GEMM>>>(
            cath, catl, chwh, chwl, 0, 0, cheb_b, out, 0, 0,
            KCAT, KCAT, TT_, TT_, 0, 0, 0, 0, 0, 1.f, 0.f, 1);
    }
}